// round 6
// baseline (speedup 1.0000x reference)
#include <cuda_runtime.h>
#include <cuda_bf16.h>
#include <math.h>
#include <stdint.h>

// ---------------- problem constants ----------------
#define VV    50000
#define OOV_N 100
#define VO    50100
#define EE    128
#define HH    256
#define BB    32
#define SS    256
#define TT    16
#define BTVO  ((size_t)BB * TT * VO)   // 25,651,200
#define LOG1EM10 (-23.025850929940457f)

// vocab mma smem strides (bf16 units)
#define BSTR 136
#define ASTR 264
#define VOCAB_SMEM (256*BSTR*2 + 64*ASTR*2 + 64*4)   // 103,680 B

// ---------------- static device scratch (no runtime alloc) ----------------
__device__ float d_zx_enc[(size_t)BB * SS * 4 * HH];
__device__ float d_zx_dec[BB * TT * 4 * HH];
__device__ float d_enc_out[(size_t)BB * SS * HH];
__device__ float d_dec_out[BB * TT * HH];
__device__ float d_ehec[2 * BB * HH];      // rows 0..31 = eh, 32..63 = ec
__device__ float d_h0c0[2 * BB * HH];      // rows 0..31 = h0, 32..63 = c0
__device__ float d_encWc[(size_t)BB * SS * HH];
__device__ float d_attn[BB * TT * HH];
__device__ float d_rowsum[BB * TT];
__device__ float d_logz[BB * TT];
__device__ float d_fixval[BB * TT * SS];
__device__ float d_copyacc[BTVO];
__device__ float d_zero[BB * HH];          // stays zero forever

__device__ volatile unsigned g_bar_cnt;
__device__ volatile unsigned g_bar_gen;

// ================= grid barrier (all CTAs co-resident) =================
__device__ __forceinline__ void grid_barrier(unsigned nblocks) {
    __threadfence();
    __syncthreads();
    if (threadIdx.x == 0) {
        unsigned gen = g_bar_gen;
        unsigned arr = atomicAdd((unsigned*)&g_bar_cnt, 1u);
        if (arr == nblocks - 1u) {
            g_bar_cnt = 0u;
            __threadfence();
            g_bar_gen = gen + 1u;
        } else {
            while (g_bar_gen == gen) { }
        }
        __threadfence();
    }
    __syncthreads();
}

// ================= small SGEMM, spill-proof: 128x64 tile, 8x4 micro =================
// C = op(A @ B + bias).  A: MxK (or gathered emb rows), B: KxN, C: MxN (ldc=N).
// M % 128 == 0, N % 64 == 0, K % 16 == 0 for all call sites.
// MODE 0: none, 1: tanh.  GATHER 1: A row r = emb[tokens[r]].
template <int MODE, int GATHER>
__global__ void __launch_bounds__(256)
sgemm_small(const float* __restrict__ A, const int* __restrict__ tokens,
            const float* __restrict__ emb, const float* __restrict__ B,
            float* __restrict__ C, int M, int N, int K,
            const float* __restrict__ bias) {
    __shared__ float As[16][132];
    __shared__ float Bs[16][68];

    const int tid  = threadIdx.x;
    const int row0 = blockIdx.y * 128;
    const int col0 = blockIdx.x * 64;
    const int tr   = tid >> 4;    // 0..15 -> rows tr*8
    const int tc   = tid & 15;    // 0..15 -> cols tc*4

    float acc[8][4];
#pragma unroll
    for (int i = 0; i < 8; i++)
#pragma unroll
        for (int j = 0; j < 4; j++) acc[i][j] = 0.f;

    for (int k0 = 0; k0 < K; k0 += 16) {
        // A tile -> As[k][r] transposed; 2 float4 per thread
#pragma unroll
        for (int h = 0; h < 2; h++) {
            int i4 = tid + 256 * h;        // 0..511
            int r  = i4 >> 2;              // 0..127
            int kq = (i4 & 3) * 4;
            const float* src;
            if (GATHER) {
                int tok = tokens[row0 + r];
                src = &emb[(size_t)tok * K + k0 + kq];
            } else {
                src = &A[(size_t)(row0 + r) * K + k0 + kq];
            }
            float4 v = *reinterpret_cast<const float4*>(src);
            As[kq + 0][r] = v.x; As[kq + 1][r] = v.y;
            As[kq + 2][r] = v.z; As[kq + 3][r] = v.w;
        }
        // B tile: 1 float4 per thread
        {
            int kk = tid >> 4, n4 = (tid & 15) * 4;
            *reinterpret_cast<float4*>(&Bs[kk][n4]) =
                *reinterpret_cast<const float4*>(&B[(size_t)(k0 + kk) * N + col0 + n4]);
        }
        __syncthreads();

#pragma unroll
        for (int kk = 0; kk < 16; kk++) {
            float4 a0 = *reinterpret_cast<const float4*>(&As[kk][tr * 8]);
            float4 a1 = *reinterpret_cast<const float4*>(&As[kk][tr * 8 + 4]);
            float4 b0 = *reinterpret_cast<const float4*>(&Bs[kk][tc * 4]);
            float a[8] = {a0.x, a0.y, a0.z, a0.w, a1.x, a1.y, a1.z, a1.w};
            float b[4] = {b0.x, b0.y, b0.z, b0.w};
#pragma unroll
            for (int i = 0; i < 8; i++)
#pragma unroll
                for (int j = 0; j < 4; j++) acc[i][j] += a[i] * b[j];
        }
        __syncthreads();
    }

#pragma unroll
    for (int i = 0; i < 8; i++) {
        int r = row0 + tr * 8 + i;
#pragma unroll
        for (int j = 0; j < 4; j++) {
            int c = col0 + tc * 4 + j;
            float v = acc[i][j];
            if (bias) v += bias[c];
            if (MODE == 1) v = tanhf(v);
            C[(size_t)r * N + c] = v;
        }
    }
}

// ================= persistent LSTM (128 CTAs x 256 threads) =================
// CTA owns 2 hidden units (8 gate-outputs), 1 thread per (gate-output, batch).
// Optional prologue: h0c0[o] = be2d[col] + ehec[row]@We2d (64x256), then barrier.
__global__ void __launch_bounds__(256, 1)
lstm_kernel(const float* __restrict__ zx, const float* __restrict__ U,
            const float* __restrict__ h0, const float* __restrict__ c0,
            float* __restrict__ hist, float* __restrict__ h_fin,
            float* __restrict__ c_fin, int steps,
            int do_prol, const float* __restrict__ ehec,
            const float* __restrict__ We2d, const float* __restrict__ be2d,
            float* __restrict__ h0c0w) {
    __shared__ float hs[256 * 33];   // [k][b] padded
    __shared__ float zs[256];        // [jj*32 + b]

    const int tid  = threadIdx.x;
    const int u0   = blockIdx.x * 2;
    const int b    = tid & 31;
    const int jj   = tid >> 5;               // 0..7
    const int gate = jj >> 1, unit = jj & 1;
    const int j    = gate * 256 + u0 + unit;
    const unsigned nblk = gridDim.x;

    if (do_prol) {
        if (tid < 128) {
            int o = blockIdx.x * 128 + tid;   // 0..16383
            int row = o >> 8, col = o & 255;
            float a = be2d[col];
            const float* er = &ehec[row * 256];
#pragma unroll 4
            for (int k = 0; k < 256; k++) a += er[k] * We2d[k * 256 + col];
            h0c0w[o] = a;
        }
        grid_barrier(nblk);
    }

    // update-role cell state (threads 0..63)
    const int ub = tid & 31;
    const int un = (tid >> 5) & 1;
    float c_reg = 0.f;
    if (tid < 64) c_reg = c0[ub * 256 + u0 + un];

    for (int s = 0; s < steps; s++) {
        // stage h_prev (32x256) transposed [k][b]
        if (s == 0) {
#pragma unroll 8
            for (int it = 0; it < 32; it++)
                hs[tid * 33 + it] = h0[it * 256 + tid];
        } else {
#pragma unroll 8
            for (int it = 0; it < 32; it++)
                hs[tid * 33 + it] = hist[((size_t)it * steps + (s - 1)) * 256 + tid];
        }
        __syncthreads();

        float a0 = zx[((size_t)b * steps + s) * 1024 + j];
        float a1 = 0.f, a2 = 0.f, a3 = 0.f;
#pragma unroll 4
        for (int k = 0; k < 256; k += 4) {
            a0 += __ldg(&U[(k + 0) * 1024 + j]) * hs[(k + 0) * 33 + b];
            a1 += __ldg(&U[(k + 1) * 1024 + j]) * hs[(k + 1) * 33 + b];
            a2 += __ldg(&U[(k + 2) * 1024 + j]) * hs[(k + 2) * 33 + b];
            a3 += __ldg(&U[(k + 3) * 1024 + j]) * hs[(k + 3) * 33 + b];
        }
        zs[jj * 32 + b] = (a0 + a1) + (a2 + a3);
        __syncthreads();

        if (tid < 64) {
            float iv = zs[(0 * 2 + un) * 32 + ub];
            float fv = zs[(1 * 2 + un) * 32 + ub];
            float gv = zs[(2 * 2 + un) * 32 + ub];
            float ov = zs[(3 * 2 + un) * 32 + ub];
            float ig = 1.f / (1.f + expf(-iv));
            float fg = 1.f / (1.f + expf(-fv));
            float og = 1.f / (1.f + expf(-ov));
            c_reg = fg * c_reg + ig * tanhf(gv);
            float h = og * tanhf(c_reg);
            hist[((size_t)ub * steps + s) * 256 + u0 + un] = h;
            if (s == steps - 1) {
                h_fin[ub * 256 + u0 + un] = h;
                c_fin[ub * 256 + u0 + un] = c_reg;
            }
        }
        grid_barrier(nblk);
    }
}

// ================= fused attention (dWa + softmax + ctx + Wout) =================
__global__ void __launch_bounds__(256)
attn_mega(const float* __restrict__ dec, const float* __restrict__ enc,
          const float* __restrict__ Wattn, const float* __restrict__ Wout,
          const float* __restrict__ bout, const int* __restrict__ x_len,
          float* __restrict__ attn_out, float* __restrict__ rowsum) {
    __shared__ float dec_s[256];
    __shared__ float q_s[256];
    __shared__ float aw_s[256];
    __shared__ float red[8];

    const int bt = blockIdx.x;
    const int b  = bt >> 4;
    const int tid = threadIdx.x;

    dec_s[tid] = dec[(size_t)bt * 256 + tid];
    if (tid == 0) rowsum[bt] = 1e-8f;   // OOV pad: 100 * 1e-10
    __syncthreads();

    // q = dec @ Wattn  (thread = output dim e)
    {
        float a = 0.f;
#pragma unroll 4
        for (int k = 0; k < 256; k++) a += dec_s[k] * Wattn[k * 256 + tid];
        q_s[tid] = a;
    }
    __syncthreads();

    // scores: thread = source pos s
    const float* er = enc + ((size_t)b * SS + tid) * 256;
    float dot = 0.f;
#pragma unroll 4
    for (int k = 0; k < 256; k += 4) {
        float4 e = *reinterpret_cast<const float4*>(&er[k]);
        dot += q_s[k] * e.x + q_s[k + 1] * e.y + q_s[k + 2] * e.z + q_s[k + 3] * e.w;
    }
    const int len = x_len[b];
    float sc = (tid < len) ? dot : -1e30f;

    float m = sc;
#pragma unroll
    for (int o = 16; o; o >>= 1) m = fmaxf(m, __shfl_xor_sync(~0u, m, o));
    if ((tid & 31) == 0) red[tid >> 5] = m;
    __syncthreads();
    float mx = red[0];
#pragma unroll
    for (int w = 1; w < 8; w++) mx = fmaxf(mx, red[w]);
    __syncthreads();

    float e = (tid < len) ? __expf(sc - mx) : 0.f;
    float sm = e;
#pragma unroll
    for (int o = 16; o; o >>= 1) sm += __shfl_xor_sync(~0u, sm, o);
    if ((tid & 31) == 0) red[tid >> 5] = sm;
    __syncthreads();
    float tot = 0.f;
#pragma unroll
    for (int w = 0; w < 8; w++) tot += red[w];
    aw_s[tid] = e / tot;
    __syncthreads();

    // ctx: thread = embedding dim
    float cx = 0.f;
    const float* eb = enc + (size_t)b * SS * 256 + tid;
    for (int s = 0; s < SS; s++) cx += aw_s[s] * eb[(size_t)s * 256];
    __syncthreads();
    q_s[tid] = cx;                 // q_s now holds ctx
    __syncthreads();

    // attn_out = tanh([ctx, dec] @ Wout + bout)
    float a2 = bout[tid];
#pragma unroll 4
    for (int k = 0; k < 256; k++) a2 += q_s[k] * Wout[k * 256 + tid];
#pragma unroll 4
    for (int k = 0; k < 256; k++) a2 += dec_s[k] * Wout[(256 + k) * 256 + tid];
    attn_out[(size_t)bt * 256 + tid] = tanhf(a2);
}

// ================= vocab GEMM on tensor cores (bf16 mma) =================
__device__ __forceinline__ uint32_t smem_u32(const void* p) {
    return (uint32_t)__cvta_generic_to_shared(p);
}
__device__ __forceinline__ void ldsm_x4(uint32_t* r, uint32_t addr) {
    asm volatile("ldmatrix.sync.aligned.m8n8.x4.shared.b16 {%0,%1,%2,%3}, [%4];"
                 : "=r"(r[0]), "=r"(r[1]), "=r"(r[2]), "=r"(r[3]) : "r"(addr));
}
__device__ __forceinline__ void ldsm_x2_trans(uint32_t* r, uint32_t addr) {
    asm volatile("ldmatrix.sync.aligned.m8n8.x2.trans.shared.b16 {%0,%1}, [%2];"
                 : "=r"(r[0]), "=r"(r[1]) : "r"(addr));
}
__device__ __forceinline__ void mma_bf16(float* d, const uint32_t* a, const uint32_t* b) {
    asm volatile("mma.sync.aligned.m16n8k16.row.col.f32.bf16.bf16.f32 "
                 "{%0,%1,%2,%3}, {%4,%5,%6,%7}, {%8,%9}, {%0,%1,%2,%3};"
                 : "+f"(d[0]), "+f"(d[1]), "+f"(d[2]), "+f"(d[3])
                 : "r"(a[0]), "r"(a[1]), "r"(a[2]), "r"(a[3]), "r"(b[0]), "r"(b[1]));
}

// One CTA per 128-col strip of Wgen; loops over all M=512 rows.
// Writes raw logits to out (row stride VO) and atomically accumulates
// per-row exp-sums (via __expf) into rowsum.
__global__ void __launch_bounds__(256)
vocab_kernel(const float* __restrict__ A,      // attn_out 512x256 fp32
             const float* __restrict__ Wgen,   // 256x50000 fp32
             float* __restrict__ out, float* __restrict__ rowsum) {
    extern __shared__ char dsm[];
    __nv_bfloat16* Bsh = (__nv_bfloat16*)dsm;                        // [256][BSTR]
    __nv_bfloat16* Ash = (__nv_bfloat16*)(dsm + 256 * BSTR * 2);     // [64][ASTR]
    float* rsumsh = (float*)(dsm + 256 * BSTR * 2 + 64 * ASTR * 2);  // [64]

    const int tid  = threadIdx.x;
    const int lane = tid & 31, wid = tid >> 5;
    const int n0   = blockIdx.x * 128;
    const int wm   = wid >> 2, wn = wid & 3;     // warps 2(m) x 4(n)
    const int m_off = wm * 32, n_off = wn * 32;

    // ---- stage B strip once: 256(k) x 128(n), fp32 -> bf16 ----
    for (int i = tid; i < 256 * 32; i += 256) {
        int k  = i >> 5;
        int n4 = (i & 31) << 2;
        int gn = n0 + n4;
        float4 v;
        if (gn + 3 < VV) {
            v = *reinterpret_cast<const float4*>(&Wgen[(size_t)k * VV + gn]);
        } else {
            float t0 = (gn + 0 < VV) ? Wgen[(size_t)k * VV + gn + 0] : 0.f;
            float t1 = (gn + 1 < VV) ? Wgen[(size_t)k * VV + gn + 1] : 0.f;
            float t2 = (gn + 2 < VV) ? Wgen[(size_t)k * VV + gn + 2] : 0.f;
            float t3 = (gn + 3 < VV) ? Wgen[(size_t)k * VV + gn + 3] : 0.f;
            v = make_float4(t0, t1, t2, t3);
        }
        __nv_bfloat162* dst = reinterpret_cast<__nv_bfloat162*>(&Bsh[k * BSTR + n4]);
        dst[0] = __floats2bfloat162_rn(v.x, v.y);
        dst[1] = __floats2bfloat162_rn(v.z, v.w);
    }
    if (tid < 64) rsumsh[tid] = 0.f;
    __syncthreads();

    for (int mb = 0; mb < 8; mb++) {
        const int m0 = mb * 64;
        // ---- stage A block: 64(m) x 256(k) ----
        for (int i = tid; i < 64 * 64; i += 256) {
            int r  = i >> 6;
            int k4 = (i & 63) << 2;
            float4 v = *reinterpret_cast<const float4*>(&A[(size_t)(m0 + r) * 256 + k4]);
            __nv_bfloat162* dst = reinterpret_cast<__nv_bfloat162*>(&Ash[r * ASTR + k4]);
            dst[0] = __floats2bfloat162_rn(v.x, v.y);
            dst[1] = __floats2bfloat162_rn(v.z, v.w);
        }
        __syncthreads();

        float acc[2][4][4];
#pragma unroll
        for (int mf = 0; mf < 2; mf++)
#pragma unroll
            for (int nf = 0; nf < 4; nf++)
#pragma unroll
                for (int q = 0; q < 4; q++) acc[mf][nf][q] = 0.f;

#pragma unroll
        for (int ks = 0; ks < 16; ks++) {
            const int k0 = ks * 16;
            uint32_t afr[2][4];
#pragma unroll
            for (int mf = 0; mf < 2; mf++) {
                const __nv_bfloat16* ap =
                    &Ash[(m_off + mf * 16 + (lane & 15)) * ASTR + k0 + (lane >> 4) * 8];
                ldsm_x4(afr[mf], smem_u32(ap));
            }
            uint32_t bfr[4][2];
#pragma unroll
            for (int nf = 0; nf < 4; nf++) {
                const __nv_bfloat16* bp =
                    &Bsh[(k0 + (lane & 15)) * BSTR + n_off + nf * 8];
                ldsm_x2_trans(bfr[nf], smem_u32(bp));
            }
#pragma unroll
            for (int mf = 0; mf < 2; mf++)
#pragma unroll
                for (int nf = 0; nf < 4; nf++)
                    mma_bf16(acc[mf][nf], afr[mf], bfr[nf]);
        }

        // ---- epilogue: store logits + __expf row partial sums ----
        float psum[4] = {0.f, 0.f, 0.f, 0.f};
#pragma unroll
        for (int mf = 0; mf < 2; mf++) {
            int gr0 = m0 + m_off + mf * 16 + (lane >> 2);
#pragma unroll
            for (int nf = 0; nf < 4; nf++) {
                int gc = n0 + n_off + nf * 8 + (lane & 3) * 2;
                float v0 = acc[mf][nf][0], v1 = acc[mf][nf][1];
                float v2 = acc[mf][nf][2], v3 = acc[mf][nf][3];
                if (gc + 1 < VV) {
                    *reinterpret_cast<float2*>(&out[(size_t)gr0 * VO + gc]) = make_float2(v0, v1);
                    *reinterpret_cast<float2*>(&out[(size_t)(gr0 + 8) * VO + gc]) = make_float2(v2, v3);
                    psum[mf * 2 + 0] += __expf(v0) + __expf(v1);
                    psum[mf * 2 + 1] += __expf(v2) + __expf(v3);
                } else if (gc < VV) {
                    out[(size_t)gr0 * VO + gc] = v0;
                    out[(size_t)(gr0 + 8) * VO + gc] = v2;
                    psum[mf * 2 + 0] += __expf(v0);
                    psum[mf * 2 + 1] += __expf(v2);
                }
            }
        }
        {
            int lr = m_off + (lane >> 2);
            atomicAdd(&rsumsh[lr + 0],  psum[0]);
            atomicAdd(&rsumsh[lr + 8],  psum[1]);
            atomicAdd(&rsumsh[lr + 16], psum[2]);
            atomicAdd(&rsumsh[lr + 24], psum[3]);
        }
        __syncthreads();
        if (tid < 64) {
            atomicAdd(&rowsum[m0 + tid], rsumsh[tid]);
            rsumsh[tid] = 0.f;
        }
        __syncthreads();
    }
}

// ================= encWc zero targets =================
__global__ void copyzero_kernel(float* __restrict__ copyacc, const int* __restrict__ xov,
                                const int* __restrict__ x_len) {
    const int bt = blockIdx.x;
    const int b  = bt >> 4;
    const int s  = threadIdx.x;
    if (s < x_len[b]) copyacc[(size_t)bt * VO + xov[b * SS + s]] = 0.f;
}

// ================= copy scores + scatter =================
__global__ void __launch_bounds__(256)
copy_scatter_kernel(const float* __restrict__ encWc, const float* __restrict__ attn,
                    const int* __restrict__ xov, const int* __restrict__ x_len,
                    float* __restrict__ copyacc, float* __restrict__ rowsum) {
    __shared__ float a[256];
    const int bt = blockIdx.x;
    const int b  = bt >> 4;
    const int tid = threadIdx.x;

    a[tid] = attn[(size_t)bt * 256 + tid];
    __syncthreads();

    if (tid < x_len[b]) {
        const float* r = encWc + ((size_t)b * SS + tid) * 256;
        float dot = 0.f;
#pragma unroll 4
        for (int k = 0; k < 256; k += 4) {
            float4 e = *reinterpret_cast<const float4*>(&r[k]);
            dot += a[k] * e.x + a[k + 1] * e.y + a[k + 2] * e.z + a[k + 3] * e.w;
        }
        float v = expf(dot);
        atomicAdd(&copyacc[(size_t)bt * VO + xov[b * SS + tid]], v);
        atomicAdd(&rowsum[bt], v);
    }
}

// ================= fixval = log(exp(logit) + copy) for touched entries =================
__global__ void fixval_kernel(const float* __restrict__ out, const float* __restrict__ copyacc,
                              const int* __restrict__ xov, const int* __restrict__ x_len,
                              float* __restrict__ fixval) {
    const int bt = blockIdx.x;
    const int b  = bt >> 4;
    const int s  = threadIdx.x;
    if (s < x_len[b]) {
        int idx = xov[b * SS + s];
        float base = (idx < VV) ? expf(out[(size_t)bt * VO + idx]) : 1e-10f;
        fixval[bt * SS + s] = logf(base + copyacc[(size_t)bt * VO + idx]);
    }
}

__global__ void logz_kernel(const float* __restrict__ rs, float* __restrict__ lz) {
    int i = threadIdx.x + blockIdx.x * blockDim.x;
    if (i < BB * TT) lz[i] = logf(rs[i]);
}

__global__ void finalize_kernel(float* __restrict__ out, const float* __restrict__ lz) {
    const int row = blockIdx.y;
    const int c4  = (blockIdx.x * 256 + threadIdx.x) * 4;
    if (c4 >= VO) return;
    float z = lz[row];
    float* p = out + (size_t)row * VO + c4;
    if (c4 + 3 < VV) {
        float4 v = *reinterpret_cast<float4*>(p);
        v.x -= z; v.y -= z; v.z -= z; v.w -= z;
        *reinterpret_cast<float4*>(p) = v;
    } else {
#pragma unroll
        for (int j = 0; j < 4; j++) {
            int c = c4 + j;
            if (c < VO) p[j] = (c < VV) ? p[j] - z : LOG1EM10 - z;
        }
    }
}

__global__ void fixwrite_kernel(float* __restrict__ out, const float* __restrict__ fixval,
                                const float* __restrict__ lz, const int* __restrict__ xov,
                                const int* __restrict__ x_len) {
    const int bt = blockIdx.x;
    const int b  = bt >> 4;
    const int s  = threadIdx.x;
    if (s < x_len[b]) {
        int idx = xov[b * SS + s];
        out[(size_t)bt * VO + idx] = fixval[bt * SS + s] - lz[bt];
    }
}

// ================= host side =================
extern "C" void kernel_launch(void* const* d_in, const int* in_sizes, int n_in,
                              void* d_out, int out_size) {
    const int*   x     = (const int*)d_in[0];
    const int*   xov   = (const int*)d_in[1];
    const int*   xlen  = (const int*)d_in[2];
    const int*   dx    = (const int*)d_in[3];
    const float* emb   = (const float*)d_in[4];
    const float* Wenc  = (const float*)d_in[5];
    const float* Uenc  = (const float*)d_in[6];
    const float* benc  = (const float*)d_in[7];
    const float* We2d  = (const float*)d_in[8];
    const float* be2d  = (const float*)d_in[9];
    const float* Wdec  = (const float*)d_in[10];
    const float* Udec  = (const float*)d_in[11];
    const float* bdec  = (const float*)d_in[12];
    const float* Wattn = (const float*)d_in[13];
    const float* Wout  = (const float*)d_in[14];
    const float* bout  = (const float*)d_in[15];
    const float* Wgen  = (const float*)d_in[16];
    const float* Wcopy = (const float*)d_in[17];
    const float* bcopy = (const float*)d_in[18];
    float* out = (float*)d_out;
    (void)in_sizes; (void)n_in; (void)out_size;

    void* p;
    cudaGetSymbolAddress(&p, d_zx_enc);  float* s_zx_enc  = (float*)p;
    cudaGetSymbolAddress(&p, d_zx_dec);  float* s_zx_dec  = (float*)p;
    cudaGetSymbolAddress(&p, d_enc_out); float* s_enc_out = (float*)p;
    cudaGetSymbolAddress(&p, d_dec_out); float* s_dec_out = (float*)p;
    cudaGetSymbolAddress(&p, d_ehec);    float* s_ehec    = (float*)p;
    cudaGetSymbolAddress(&p, d_h0c0);    float* s_h0c0    = (float*)p;
    cudaGetSymbolAddress(&p, d_encWc);   float* s_encWc   = (float*)p;
    cudaGetSymbolAddress(&p, d_attn);    float* s_attn    = (float*)p;
    cudaGetSymbolAddress(&p, d_rowsum);  float* s_rowsum  = (float*)p;
    cudaGetSymbolAddress(&p, d_logz);    float* s_logz    = (float*)p;
    cudaGetSymbolAddress(&p, d_fixval);  float* s_fixval  = (float*)p;
    cudaGetSymbolAddress(&p, d_copyacc); float* s_copyacc = (float*)p;
    cudaGetSymbolAddress(&p, d_zero);    float* s_zero    = (float*)p;

    cudaFuncSetAttribute(vocab_kernel,
                         cudaFuncAttributeMaxDynamicSharedMemorySize, VOCAB_SMEM + 256);

    // 1. zx_enc = emb[x] @ Wenc + benc   (embedding gather fused)
    {
        dim3 g(1024 / 64, (BB * SS) / 128);
        sgemm_small<0, 1><<<g, 256>>>(nullptr, x, emb, Wenc, s_zx_enc,
                                      BB * SS, 4 * HH, EE, benc);
    }
    // 2. zx_dec = emb[dec_x] @ Wdec + bdec
    {
        dim3 g(1024 / 64, (BB * TT) / 128);
        sgemm_small<0, 1><<<g, 256>>>(nullptr, dx, emb, Wdec, s_zx_dec,
                                      BB * TT, 4 * HH, EE, bdec);
    }
    // 3. encoder LSTM
    lstm_kernel<<<128, 256>>>(s_zx_enc, Uenc, s_zero, s_zero,
                              s_enc_out, s_ehec, s_ehec + BB * HH, SS,
                              0, nullptr, nullptr, nullptr, nullptr);
    // 4. decoder LSTM (h0c0 GEMM fused in prologue); final h,c -> output tail
    lstm_kernel<<<128, 256>>>(s_zx_dec, Udec, s_h0c0, s_h0c0 + BB * HH,
                              s_dec_out, out + BTVO, out + BTVO + BB * HH, TT,
                              1, s_ehec, We2d, be2d, s_h0c0);
    // 5. fused attention (also inits rowsum = 1e-8)
    attn_mega<<<BB * TT, 256>>>(s_dec_out, s_enc_out, Wattn, Wout, bout, xlen,
                                s_attn, s_rowsum);
    // 6. vocab GEMM (tensor cores): logits -> out, exp-rowsums -> rowsum   [PROFILED]
    vocab_kernel<<<(VV + 127) / 128, 256, VOCAB_SMEM>>>(s_attn, Wgen, out, s_rowsum);
    // 7. encWc = tanh(enc_out @ Wcopy + bcopy)
    {
        dim3 g(256 / 64, (BB * SS) / 128);
        sgemm_small<1, 0><<<g, 256>>>(s_enc_out, nullptr, nullptr, Wcopy, s_encWc,
                                      BB * SS, HH, HH, bcopy);
    }
    // 8-9. zero scatter targets, scatter copy scores
    copyzero_kernel<<<BB * TT, 256>>>(s_copyacc, xov, xlen);
    copy_scatter_kernel<<<BB * TT, 256>>>(s_encWc, s_attn, xov, xlen, s_copyacc, s_rowsum);
    // 10. fixval (reads raw logits before finalize)
    fixval_kernel<<<BB * TT, 256>>>(out, s_copyacc, xov, xlen, s_fixval);
    // 11. logZ
    logz_kernel<<<2, 256>>>(s_rowsum, s_logz);
    // 12. normalize whole tensor
    {
        dim3 g((VO + 1023) / 1024, BB * TT);
        finalize_kernel<<<g, 256>>>(out, s_logz);
    }
    // 13. overwrite touched entries
    fixwrite_kernel<<<BB * TT, 256>>>(out, s_fixval, s_logz, xov, xlen);
}

// round 7
// speedup vs baseline: 1.5675x; 1.5675x over previous
#include <cuda_runtime.h>
#include <cuda_bf16.h>
#include <math.h>
#include <stdint.h>

#define VV    50000
#define OOV_N 100
#define VO    50100
#define EE    128
#define HH    256
#define BB    32
#define SS    256
#define TT    16
#define BTVO  ((size_t)BB * TT * VO)
#define LOG1EM10 (-23.025850929940457f)

#define BSTR 136
#define ASTR 264
#define VOCAB_SMEM (256*BSTR*2 + 64*ASTR*2 + 64*4)

// lstm cluster smem floats: U 32768 + hbuf 512 + zp 1024 + zs 256 + zxs 256 + hown 128
#define LSTM_SMEM_BYTES ((32768 + 512 + 1024 + 256 + 256 + 128) * 4)

__device__ float d_zx_enc[(size_t)BB * SS * 4 * HH];
__device__ float d_zx_dec[BB * TT * 4 * HH];
__device__ float d_enc_out[(size_t)BB * SS * HH];
__device__ float d_dec_out[BB * TT * HH];
__device__ float d_ehec[2 * BB * HH];
__device__ float d_h0c0[2 * BB * HH];
__device__ float d_encWc[(size_t)BB * SS * HH];
__device__ float d_attn[BB * TT * HH];
__device__ float d_rowsum[BB * TT];
__device__ float d_logz[BB * TT];
__device__ float d_fixval[BB * TT * SS];
__device__ float d_copyacc[BTVO];
__device__ float d_zero[BB * HH];

__device__ __forceinline__ uint32_t smem_u32(const void* p) {
    return (uint32_t)__cvta_generic_to_shared(p);
}
__device__ __forceinline__ float dsmem_ld_f32(uint32_t laddr, uint32_t rank) {
    uint32_t ra; float v;
    asm volatile("mapa.shared::cluster.u32 %0, %1, %2;" : "=r"(ra) : "r"(laddr), "r"(rank));
    asm volatile("ld.shared::cluster.f32 %0, [%1];" : "=f"(v) : "r"(ra));
    return v;
}
#define CLUSTER_SYNC_() do { \
    asm volatile("barrier.cluster.arrive.aligned;" ::: "memory"); \
    asm volatile("barrier.cluster.wait.aligned;" ::: "memory"); \
} while (0)

// ===== cluster LSTM: 16 clusters x 8 CTAs, 512 thr. Cluster owns 2 batches;
// CTA rank r owns units [r*32,r*32+32); U slice resident in smem. =====
__global__ void __launch_bounds__(512, 1) __cluster_dims__(8, 1, 1)
lstm_cluster(const float* __restrict__ zx, const float* __restrict__ U,
             const float* __restrict__ h0, const float* __restrict__ c0,
             float* __restrict__ hist, float* __restrict__ h_fin,
             float* __restrict__ c_fin, int steps) {
    extern __shared__ float sm[];
    float4* Us4  = (float4*)sm;            // 128c x 64 quads, swizzled
    float*  Usf  = sm;
    float*  hbuf = sm + 128 * 256;         // [2b][256]
    float*  zp   = hbuf + 512;             // [4hf][2b*128c]
    float*  zs   = zp + 1024;              // [2b][128c]
    float*  zxs  = zs + 256;               // [2b][128c]
    float*  hown = zxs + 256;              // [2buf][2b][32ul]

    const int tid = threadIdx.x;
    uint32_t rk; asm("mov.u32 %0, %%cluster_ctarank;" : "=r"(rk));
    const int r   = (int)rk;
    const int b0g = (blockIdx.x >> 3) * 2;

    for (int i = tid; i < 128 * 256; i += 512) {
        int c = i & 127, k = i >> 7;
        int g = c >> 5, ul = c & 31;
        float v = U[(size_t)k * 1024 + g * 256 + r * 32 + ul];
        int q = (k >> 2) ^ (c & 7);
        Usf[(c * 64 + q) * 4 + (k & 3)] = v;
    }
    float c_reg = 0.f;
    if (tid < 64) {
        int b = tid >> 5, ul = tid & 31;
        hown[(0 * 2 + b) * 32 + ul] = h0[(size_t)(b0g + b) * 256 + r * 32 + ul];
        c_reg = c0[(size_t)(b0g + b) * 256 + r * 32 + ul];
    }
    __syncthreads();
    CLUSTER_SYNC_();

    const uint32_t hown_u32 = smem_u32(hown);
    const int c  = tid & 127;
    const int hf = tid >> 7;
    const int cx = c & 7;
    int cur = 0;

    for (int s = 0; s < steps; s++) {
        {   // pull h (1 value/thread) from peer CTAs
            int b = tid >> 8, u = tid & 255;
            uint32_t la = hown_u32 + (uint32_t)(((cur * 2 + b) * 32 + (u & 31)) * 4);
            hbuf[b * 256 + u] = dsmem_ld_f32(la, (uint32_t)(u >> 5));
        }
        if (tid < 256) {
            int b = tid >> 7, cc = tid & 127;
            int g = cc >> 5, ul = cc & 31;
            zxs[tid] = zx[((size_t)(b0g + b) * steps + s) * 1024 + g * 256 + r * 32 + ul];
        }
        __syncthreads();

        {   // gemv: thread (c,hf) covers k in [hf*64, hf*64+64), both batches
            float a00 = 0.f, a01 = 0.f, a02 = 0.f, a03 = 0.f;
            float a10 = 0.f, a11 = 0.f, a12 = 0.f, a13 = 0.f;
            const float4* h40 = (const float4*)&hbuf[0];
            const float4* h41 = (const float4*)&hbuf[256];
            const int kq0 = hf * 16;
#pragma unroll
            for (int t = 0; t < 16; t++) {
                int kq = kq0 + t;
                float4 u4 = Us4[c * 64 + (kq ^ cx)];
                float4 hA = h40[kq];
                float4 hB = h41[kq];
                a00 += u4.x * hA.x; a01 += u4.y * hA.y;
                a02 += u4.z * hA.z; a03 += u4.w * hA.w;
                a10 += u4.x * hB.x; a11 += u4.y * hB.y;
                a12 += u4.z * hB.z; a13 += u4.w * hB.w;
            }
            zp[hf * 256 + c]       = (a00 + a01) + (a02 + a03);
            zp[hf * 256 + 128 + c] = (a10 + a11) + (a12 + a13);
        }
        __syncthreads();
        if (tid < 256)
            zs[tid] = zxs[tid] + ((zp[tid] + zp[256 + tid]) + (zp[512 + tid] + zp[768 + tid]));
        __syncthreads();
        if (tid < 64) {
            int b = tid >> 5, ul = tid & 31;
            float iv = zs[b * 128 + 0 * 32 + ul];
            float fv = zs[b * 128 + 1 * 32 + ul];
            float gv = zs[b * 128 + 2 * 32 + ul];
            float ov = zs[b * 128 + 3 * 32 + ul];
            float ig = 1.f / (1.f + expf(-iv));
            float fg = 1.f / (1.f + expf(-fv));
            float og = 1.f / (1.f + expf(-ov));
            c_reg = fg * c_reg + ig * tanhf(gv);
            float h = og * tanhf(c_reg);
            hown[((cur ^ 1) * 2 + b) * 32 + ul] = h;
            hist[((size_t)(b0g + b) * steps + s) * 256 + r * 32 + ul] = h;
            if (s == steps - 1) {
                h_fin[(size_t)(b0g + b) * 256 + r * 32 + ul] = h;
                c_fin[(size_t)(b0g + b) * 256 + r * 32 + ul] = c_reg;
            }
        }
        CLUSTER_SYNC_();
        cur ^= 1;
    }
}

// ===== h0c0 = [eh;ec] @ We2d + be2d =====
__global__ void __launch_bounds__(256)
h0c0_kernel(const float* __restrict__ ehec, const float* __restrict__ We2d,
            const float* __restrict__ be2d, float* __restrict__ h0c0) {
    const int row = blockIdx.x, col = threadIdx.x;
    float a = be2d[col];
    const float* er = &ehec[row * 256];
#pragma unroll 4
    for (int k = 0; k < 256; k++) a += er[k] * We2d[k * 256 + col];
    h0c0[row * 256 + col] = a;
}

// ===== small SGEMM 128x64 tile, 8x4 micro =====
template <int MODE, int GATHER>
__global__ void __launch_bounds__(256)
sgemm_small(const float* __restrict__ A, const int* __restrict__ tokens,
            const float* __restrict__ emb, const float* __restrict__ B,
            float* __restrict__ C, int M, int N, int K,
            const float* __restrict__ bias) {
    __shared__ float As[16][132];
    __shared__ float Bs[16][68];
    const int tid  = threadIdx.x;
    const int row0 = blockIdx.y * 128;
    const int col0 = blockIdx.x * 64;
    const int tr   = tid >> 4, tc = tid & 15;

    float acc[8][4];
#pragma unroll
    for (int i = 0; i < 8; i++)
#pragma unroll
        for (int j = 0; j < 4; j++) acc[i][j] = 0.f;

    for (int k0 = 0; k0 < K; k0 += 16) {
#pragma unroll
        for (int h = 0; h < 2; h++) {
            int i4 = tid + 256 * h;
            int r  = i4 >> 2;
            int kq = (i4 & 3) * 4;
            const float* src;
            if (GATHER) src = &emb[(size_t)tokens[row0 + r] * K + k0 + kq];
            else        src = &A[(size_t)(row0 + r) * K + k0 + kq];
            float4 v = *reinterpret_cast<const float4*>(src);
            As[kq + 0][r] = v.x; As[kq + 1][r] = v.y;
            As[kq + 2][r] = v.z; As[kq + 3][r] = v.w;
        }
        {
            int kk = tid >> 4, n4 = (tid & 15) * 4;
            *reinterpret_cast<float4*>(&Bs[kk][n4]) =
                *reinterpret_cast<const float4*>(&B[(size_t)(k0 + kk) * N + col0 + n4]);
        }
        __syncthreads();
#pragma unroll
        for (int kk = 0; kk < 16; kk++) {
            float4 a0 = *reinterpret_cast<const float4*>(&As[kk][tr * 8]);
            float4 a1 = *reinterpret_cast<const float4*>(&As[kk][tr * 8 + 4]);
            float4 b0 = *reinterpret_cast<const float4*>(&Bs[kk][tc * 4]);
            float a[8] = {a0.x, a0.y, a0.z, a0.w, a1.x, a1.y, a1.z, a1.w};
            float b[4] = {b0.x, b0.y, b0.z, b0.w};
#pragma unroll
            for (int i = 0; i < 8; i++)
#pragma unroll
                for (int j = 0; j < 4; j++) acc[i][j] += a[i] * b[j];
        }
        __syncthreads();
    }
#pragma unroll
    for (int i = 0; i < 8; i++) {
        int r = row0 + tr * 8 + i;
#pragma unroll
        for (int j = 0; j < 4; j++) {
            int c = col0 + tc * 4 + j;
            float v = acc[i][j];
            if (bias) v += bias[c];
            if (MODE == 1) v = tanhf(v);
            C[(size_t)r * N + c] = v;
        }
    }
}

// ===== fused attention =====
__global__ void __launch_bounds__(256)
attn_mega(const float* __restrict__ dec, const float* __restrict__ enc,
          const float* __restrict__ Wattn, const float* __restrict__ Wout,
          const float* __restrict__ bout, const int* __restrict__ x_len,
          float* __restrict__ attn_out, float* __restrict__ rowsum) {
    __shared__ float dec_s[256];
    __shared__ float q_s[256];
    __shared__ float aw_s[256];
    __shared__ float red[8];
    const int bt = blockIdx.x, b = bt >> 4, tid = threadIdx.x;

    dec_s[tid] = dec[(size_t)bt * 256 + tid];
    if (tid == 0) rowsum[bt] = 1e-8f;
    __syncthreads();
    {
        float a = 0.f;
#pragma unroll 4
        for (int k = 0; k < 256; k++) a += dec_s[k] * Wattn[k * 256 + tid];
        q_s[tid] = a;
    }
    __syncthreads();
    const float* er = enc + ((size_t)b * SS + tid) * 256;
    float dot = 0.f;
#pragma unroll 4
    for (int k = 0; k < 256; k += 4) {
        float4 e = *reinterpret_cast<const float4*>(&er[k]);
        dot += q_s[k] * e.x + q_s[k + 1] * e.y + q_s[k + 2] * e.z + q_s[k + 3] * e.w;
    }
    const int len = x_len[b];
    float sc = (tid < len) ? dot : -1e30f;
    float m = sc;
#pragma unroll
    for (int o = 16; o; o >>= 1) m = fmaxf(m, __shfl_xor_sync(~0u, m, o));
    if ((tid & 31) == 0) red[tid >> 5] = m;
    __syncthreads();
    float mx = red[0];
#pragma unroll
    for (int w = 1; w < 8; w++) mx = fmaxf(mx, red[w]);
    __syncthreads();
    float e = (tid < len) ? __expf(sc - mx) : 0.f;
    float sm = e;
#pragma unroll
    for (int o = 16; o; o >>= 1) sm += __shfl_xor_sync(~0u, sm, o);
    if ((tid & 31) == 0) red[tid >> 5] = sm;
    __syncthreads();
    float tot = 0.f;
#pragma unroll
    for (int w = 0; w < 8; w++) tot += red[w];
    aw_s[tid] = e / tot;
    __syncthreads();
    float cx = 0.f;
    const float* eb = enc + (size_t)b * SS * 256 + tid;
    for (int s = 0; s < SS; s++) cx += aw_s[s] * eb[(size_t)s * 256];
    __syncthreads();
    q_s[tid] = cx;
    __syncthreads();
    float a2 = bout[tid];
#pragma unroll 4
    for (int k = 0; k < 256; k++) a2 += q_s[k] * Wout[k * 256 + tid];
#pragma unroll 4
    for (int k = 0; k < 256; k++) a2 += dec_s[k] * Wout[(256 + k) * 256 + tid];
    attn_out[(size_t)bt * 256 + tid] = tanhf(a2);
}

// ===== vocab GEMM (bf16 mma) =====
__device__ __forceinline__ void ldsm_x4(uint32_t* r, uint32_t addr) {
    asm volatile("ldmatrix.sync.aligned.m8n8.x4.shared.b16 {%0,%1,%2,%3}, [%4];"
                 : "=r"(r[0]), "=r"(r[1]), "=r"(r[2]), "=r"(r[3]) : "r"(addr));
}
__device__ __forceinline__ void ldsm_x2_trans(uint32_t* r, uint32_t addr) {
    asm volatile("ldmatrix.sync.aligned.m8n8.x2.trans.shared.b16 {%0,%1}, [%2];"
                 : "=r"(r[0]), "=r"(r[1]) : "r"(addr));
}
__device__ __forceinline__ void mma_bf16(float* d, const uint32_t* a, const uint32_t* b) {
    asm volatile("mma.sync.aligned.m16n8k16.row.col.f32.bf16.bf16.f32 "
                 "{%0,%1,%2,%3}, {%4,%5,%6,%7}, {%8,%9}, {%0,%1,%2,%3};"
                 : "+f"(d[0]), "+f"(d[1]), "+f"(d[2]), "+f"(d[3])
                 : "r"(a[0]), "r"(a[1]), "r"(a[2]), "r"(a[3]), "r"(b[0]), "r"(b[1]));
}

__global__ void __launch_bounds__(256)
vocab_kernel(const float* __restrict__ A, const float* __restrict__ Wgen,
             float* __restrict__ out, float* __restrict__ rowsum) {
    extern __shared__ char dsm[];
    __nv_bfloat16* Bsh = (__nv_bfloat16*)dsm;
    __nv_bfloat16* Ash = (__nv_bfloat16*)(dsm + 256 * BSTR * 2);
    float* rsumsh = (float*)(dsm + 256 * BSTR * 2 + 64 * ASTR * 2);

    const int tid  = threadIdx.x;
    const int lane = tid & 31, wid = tid >> 5;
    const int n0   = blockIdx.x * 128;
    const int m_off = (wid >> 2) * 32, n_off = (wid & 3) * 32;

    for (int i = tid; i < 256 * 32; i += 256) {
        int k = i >> 5, n4 = (i & 31) << 2, gn = n0 + n4;
        float4 v;
        if (gn + 3 < VV) {
            v = *reinterpret_cast<const float4*>(&Wgen[(size_t)k * VV + gn]);
        } else {
            v.x = (gn + 0 < VV) ? Wgen[(size_t)k * VV + gn + 0] : 0.f;
            v.y = (gn + 1 < VV) ? Wgen[(size_t)k * VV + gn + 1] : 0.f;
            v.z = (gn + 2 < VV) ? Wgen[(size_t)k * VV + gn + 2] : 0.f;
            v.w = (gn + 3 < VV) ? Wgen[(size_t)k * VV + gn + 3] : 0.f;
        }
        __nv_bfloat162* dst = reinterpret_cast<__nv_bfloat162*>(&Bsh[k * BSTR + n4]);
        dst[0] = __floats2bfloat162_rn(v.x, v.y);
        dst[1] = __floats2bfloat162_rn(v.z, v.w);
    }
    if (tid < 64) rsumsh[tid] = 0.f;
    __syncthreads();

    for (int mb = 0; mb < 8; mb++) {
        const int m0 = mb * 64;
        for (int i = tid; i < 64 * 64; i += 256) {
            int r = i >> 6, k4 = (i & 63) << 2;
            float4 v = *reinterpret_cast<const float4*>(&A[(size_t)(m0 + r) * 256 + k4]);
            __nv_bfloat162* dst = reinterpret_cast<__nv_bfloat162*>(&Ash[r * ASTR + k4]);
            dst[0] = __floats2bfloat162_rn(v.x, v.y);
            dst[1] = __floats2bfloat162_rn(v.z, v.w);
        }
        __syncthreads();

        float acc[2][4][4];
#pragma unroll
        for (int mf = 0; mf < 2; mf++)
#pragma unroll
            for (int nf = 0; nf < 4; nf++)
#pragma unroll
                for (int q = 0; q < 4; q++) acc[mf][nf][q] = 0.f;

#pragma unroll
        for (int ks = 0; ks < 16; ks++) {
            const int k0 = ks * 16;
            uint32_t afr[2][4], bfr[4][2];
#pragma unroll
            for (int mf = 0; mf < 2; mf++)
                ldsm_x4(afr[mf], smem_u32(
                    &Ash[(m_off + mf * 16 + (lane & 15)) * ASTR + k0 + (lane >> 4) * 8]));
#pragma unroll
            for (int nf = 0; nf < 4; nf++)
                ldsm_x2_trans(bfr[nf], smem_u32(
                    &Bsh[(k0 + (lane & 15)) * BSTR + n_off + nf * 8]));
#pragma unroll
            for (int mf = 0; mf < 2; mf++)
#pragma unroll
                for (int nf = 0; nf < 4; nf++)
                    mma_bf16(acc[mf][nf], afr[mf], bfr[nf]);
        }

        float psum[4] = {0.f, 0.f, 0.f, 0.f};
#pragma unroll
        for (int mf = 0; mf < 2; mf++) {
            int gr0 = m0 + m_off + mf * 16 + (lane >> 2);
#pragma unroll
            for (int nf = 0; nf < 4; nf++) {
                int gc = n0 + n_off + nf * 8 + (lane & 3) * 2;
                float v0 = acc[mf][nf][0], v1 = acc[mf][nf][1];
                float v2 = acc[mf][nf][2], v3 = acc[mf][nf][3];
                if (gc + 1 < VV) {
                    *reinterpret_cast<float2*>(&out[(size_t)gr0 * VO + gc]) = make_float2(v0, v1);
                    *reinterpret_cast<float2*>(&out[(size_t)(gr0 + 8) * VO + gc]) = make_float2(v2, v3);
                    psum[mf * 2 + 0] += __expf(v0) + __expf(v1);
                    psum[mf * 2 + 1] += __expf(v2) + __expf(v3);
                } else if (gc < VV) {
                    out[(size_t)gr0 * VO + gc] = v0;
                    out[(size_t)(gr0 + 8) * VO + gc] = v2;
                    psum[mf * 2 + 0] += __expf(v0);
                    psum[mf * 2 + 1] += __expf(v2);
                }
            }
        }
        {
            int lr = m_off + (lane >> 2);
            atomicAdd(&rsumsh[lr + 0],  psum[0]);
            atomicAdd(&rsumsh[lr + 8],  psum[1]);
            atomicAdd(&rsumsh[lr + 16], psum[2]);
            atomicAdd(&rsumsh[lr + 24], psum[3]);
        }
        __syncthreads();
        if (tid < 64) {
            atomicAdd(&rowsum[m0 + tid], rsumsh[tid]);
            rsumsh[tid] = 0.f;
        }
        __syncthreads();
    }
}

__global__ void copyzero_kernel(float* __restrict__ copyacc, const int* __restrict__ xov,
                                const int* __restrict__ x_len) {
    const int bt = blockIdx.x, b = bt >> 4, s = threadIdx.x;
    if (s < x_len[b]) copyacc[(size_t)bt * VO + xov[b * SS + s]] = 0.f;
}

__global__ void __launch_bounds__(256)
copy_scatter_kernel(const float* __restrict__ encWc, const float* __restrict__ attn,
                    const int* __restrict__ xov, const int* __restrict__ x_len,
                    float* __restrict__ copyacc, float* __restrict__ rowsum) {
    __shared__ float a[256];
    const int bt = blockIdx.x, b = bt >> 4, tid = threadIdx.x;
    a[tid] = attn[(size_t)bt * 256 + tid];
    __syncthreads();
    if (tid < x_len[b]) {
        const float* r = encWc + ((size_t)b * SS + tid) * 256;
        float dot = 0.f;
#pragma unroll 4
        for (int k = 0; k < 256; k += 4) {
            float4 e = *reinterpret_cast<const float4*>(&r[k]);
            dot += a[k] * e.x + a[k + 1] * e.y + a[k + 2] * e.z + a[k + 3] * e.w;
        }
        float v = expf(dot);
        atomicAdd(&copyacc[(size_t)bt * VO + xov[b * SS + tid]], v);
        atomicAdd(&rowsum[bt], v);
    }
}

__global__ void fixval_kernel(const float* __restrict__ out, const float* __restrict__ copyacc,
                              const int* __restrict__ xov, const int* __restrict__ x_len,
                              float* __restrict__ fixval) {
    const int bt = blockIdx.x, b = bt >> 4, s = threadIdx.x;
    if (s < x_len[b]) {
        int idx = xov[b * SS + s];
        float base = (idx < VV) ? expf(out[(size_t)bt * VO + idx]) : 1e-10f;
        fixval[bt * SS + s] = logf(base + copyacc[(size_t)bt * VO + idx]);
    }
}

__global__ void logz_kernel(const float* __restrict__ rs, float* __restrict__ lz) {
    int i = threadIdx.x + blockIdx.x * blockDim.x;
    if (i < BB * TT) lz[i] = logf(rs[i]);
}

__global__ void finalize_kernel(float* __restrict__ out, const float* __restrict__ lz) {
    const int row = blockIdx.y;
    const int c4  = (blockIdx.x * 256 + threadIdx.x) * 4;
    if (c4 >= VO) return;
    float z = lz[row];
    float* p = out + (size_t)row * VO + c4;
    if (c4 + 3 < VV) {
        float4 v = *reinterpret_cast<float4*>(p);
        v.x -= z; v.y -= z; v.z -= z; v.w -= z;
        *reinterpret_cast<float4*>(p) = v;
    } else {
#pragma unroll
        for (int j = 0; j < 4; j++) {
            int c = c4 + j;
            if (c < VO) p[j] = (c < VV) ? p[j] - z : LOG1EM10 - z;
        }
    }
}

__global__ void fixwrite_kernel(float* __restrict__ out, const float* __restrict__ fixval,
                                const float* __restrict__ lz, const int* __restrict__ xov,
                                const int* __restrict__ x_len) {
    const int bt = blockIdx.x, b = bt >> 4, s = threadIdx.x;
    if (s < x_len[b]) {
        int idx = xov[b * SS + s];
        out[(size_t)bt * VO + idx] = fixval[bt * SS + s] - lz[bt];
    }
}

extern "C" void kernel_launch(void* const* d_in, const int* in_sizes, int n_in,
                              void* d_out, int out_size) {
    const int*   x     = (const int*)d_in[0];
    const int*   xov   = (const int*)d_in[1];
    const int*   xlen  = (const int*)d_in[2];
    const int*   dx    = (const int*)d_in[3];
    const float* emb   = (const float*)d_in[4];
    const float* Wenc  = (const float*)d_in[5];
    const float* Uenc  = (const float*)d_in[6];
    const float* benc  = (const float*)d_in[7];
    const float* We2d  = (const float*)d_in[8];
    const float* be2d  = (const float*)d_in[9];
    const float* Wdec  = (const float*)d_in[10];
    const float* Udec  = (const float*)d_in[11];
    const float* bdec  = (const float*)d_in[12];
    const float* Wattn = (const float*)d_in[13];
    const float* Wout  = (const float*)d_in[14];
    const float* bout  = (const float*)d_in[15];
    const float* Wgen  = (const float*)d_in[16];
    const float* Wcopy = (const float*)d_in[17];
    const float* bcopy = (const float*)d_in[18];
    float* out = (float*)d_out;
    (void)in_sizes; (void)n_in; (void)out_size;

    void* p;
    cudaGetSymbolAddress(&p, d_zx_enc);  float* s_zx_enc  = (float*)p;
    cudaGetSymbolAddress(&p, d_zx_dec);  float* s_zx_dec  = (float*)p;
    cudaGetSymbolAddress(&p, d_enc_out); float* s_enc_out = (float*)p;
    cudaGetSymbolAddress(&p, d_dec_out); float* s_dec_out = (float*)p;
    cudaGetSymbolAddress(&p, d_ehec);    float* s_ehec    = (float*)p;
    cudaGetSymbolAddress(&p, d_h0c0);    float* s_h0c0    = (float*)p;
    cudaGetSymbolAddress(&p, d_encWc);   float* s_encWc   = (float*)p;
    cudaGetSymbolAddress(&p, d_attn);    float* s_attn    = (float*)p;
    cudaGetSymbolAddress(&p, d_rowsum);  float* s_rowsum  = (float*)p;
    cudaGetSymbolAddress(&p, d_logz);    float* s_logz    = (float*)p;
    cudaGetSymbolAddress(&p, d_fixval);  float* s_fixval  = (float*)p;
    cudaGetSymbolAddress(&p, d_copyacc); float* s_copyacc = (float*)p;
    cudaGetSymbolAddress(&p, d_zero);    float* s_zero    = (float*)p;

    cudaFuncSetAttribute(vocab_kernel,
                         cudaFuncAttributeMaxDynamicSharedMemorySize, VOCAB_SMEM + 256);
    cudaFuncSetAttribute(lstm_cluster,
                         cudaFuncAttributeMaxDynamicSharedMemorySize, LSTM_SMEM_BYTES);

    // 1-2. zx precompute (embedding gather fused)
    {
        dim3 g(1024 / 64, (BB * SS) / 128);
        sgemm_small<0, 1><<<g, 256>>>(nullptr, x, emb, Wenc, s_zx_enc,
                                      BB * SS, 4 * HH, EE, benc);
    }
    {
        dim3 g(1024 / 64, (BB * TT) / 128);
        sgemm_small<0, 1><<<g, 256>>>(nullptr, dx, emb, Wdec, s_zx_dec,
                                      BB * TT, 4 * HH, EE, bdec);
    }
    // 3. encoder LSTM (clustered)
    lstm_cluster<<<128, 512, LSTM_SMEM_BYTES>>>(
        s_zx_enc, Uenc, s_zero, s_zero, s_enc_out,
        s_ehec, s_ehec + BB * HH, SS);
    // 4. h0/c0
    h0c0_kernel<<<64, 256>>>(s_ehec, We2d, be2d, s_h0c0);
    // 5. decoder LSTM (final h,c -> output tail)
    lstm_cluster<<<128, 512, LSTM_SMEM_BYTES>>>(
        s_zx_dec, Udec, s_h0c0, s_h0c0 + BB * HH, s_dec_out,
        out + BTVO, out + BTVO + BB * HH, TT);
    // 6. fused attention (also inits rowsum)
    attn_mega<<<BB * TT, 256>>>(s_dec_out, s_enc_out, Wattn, Wout, bout, xlen,
                                s_attn, s_rowsum);
    // 7. vocab GEMM (tensor cores)
    vocab_kernel<<<(VV + 127) / 128, 256, VOCAB_SMEM>>>(s_attn, Wgen, out, s_rowsum);
    // 8. encWc = tanh(enc_out @ Wcopy + bcopy)
    {
        dim3 g(256 / 64, (BB * SS) / 128);
        sgemm_small<1, 0><<<g, 256>>>(s_enc_out, nullptr, nullptr, Wcopy, s_encWc,
                                      BB * SS, HH, HH, bcopy);
    }
    // 9-10. scatter copy scores
    copyzero_kernel<<<BB * TT, 256>>>(s_copyacc, xov, xlen);
    copy_scatter_kernel<<<BB * TT, 256>>>(s_encWc, s_attn, xov, xlen, s_copyacc, s_rowsum);
    // 11. fixval (raw logits + copy mass)
    fixval_kernel<<<BB * TT, 256>>>(out, s_copyacc, xov, xlen, s_fixval);
    // 12. logZ
    logz_kernel<<<2, 256>>>(s_rowsum, s_logz);
    // 13. normalize
    {
        dim3 g((VO + 1023) / 1024, BB * TT);
        finalize_kernel<<<g, 256>>>(out, s_logz);
    }
    // 14. touched entries
    fixwrite_kernel<<<BB * TT, 256>>>(out, s_fixval, s_logz, xov, xlen);
}

// round 8
// speedup vs baseline: 1.5800x; 1.0080x over previous
#include <cuda_runtime.h>
#include <cuda_bf16.h>
#include <math.h>
#include <stdint.h>

#define VV    50000
#define OOV_N 100
#define VO    50100
#define EE    128
#define HH    256
#define BB    32
#define SS    256
#define TT    16
#define BTVO  ((size_t)BB * TT * VO)
#define LOG1EM10 (-23.025850929940457f)

#define BSTR 136
#define ASTR 264
#define VOCAB_SMEM (256*BSTR*2 + 64*ASTR*2 + 64*4)

// lstm cluster smem floats: U 32768 + hbuf 512 + zp 1024 + zs 256 + zxs 256 + hown 128
#define LSTM_SMEM_BYTES ((32768 + 512 + 1024 + 256 + 256 + 128) * 4)

__device__ float d_zx_enc[(size_t)BB * SS * 4 * HH];
__device__ float d_zx_dec[BB * TT * 4 * HH];
__device__ float d_enc_out[(size_t)BB * SS * HH];
__device__ float d_dec_out[BB * TT * HH];
__device__ float d_ehec[2 * BB * HH];
__device__ float d_h0c0[2 * BB * HH];
__device__ float d_encWc[(size_t)BB * SS * HH];
__device__ float d_attn[BB * TT * HH];
__device__ float d_rowsum[BB * TT];
__device__ float d_logz[BB * TT];
__device__ float d_fixval[BB * TT * SS];
__device__ float d_copyacc[BTVO];
__device__ float d_zero[BB * HH];

__device__ __forceinline__ uint32_t smem_u32(const void* p) {
    return (uint32_t)__cvta_generic_to_shared(p);
}
__device__ __forceinline__ float4 dsmem_ld_f32x4(uint32_t laddr, uint32_t rank) {
    uint32_t ra; float4 v;
    asm volatile("mapa.shared::cluster.u32 %0, %1, %2;" : "=r"(ra) : "r"(laddr), "r"(rank));
    asm volatile("ld.shared::cluster.v4.f32 {%0,%1,%2,%3}, [%4];"
                 : "=f"(v.x), "=f"(v.y), "=f"(v.z), "=f"(v.w) : "r"(ra));
    return v;
}
#define CLUSTER_SYNC_() do { \
    asm volatile("barrier.cluster.arrive.aligned;" ::: "memory"); \
    asm volatile("barrier.cluster.wait.aligned;" ::: "memory"); \
} while (0)

// ===== cluster LSTM: 16 clusters x 8 CTAs, 512 thr. Cluster owns 2 batches;
// CTA rank r owns units [r*32,r*32+32); U slice resident in smem. =====
__global__ void __launch_bounds__(512, 1) __cluster_dims__(8, 1, 1)
lstm_cluster(const float* __restrict__ zx, const float* __restrict__ U,
             const float* __restrict__ h0, const float* __restrict__ c0,
             float* __restrict__ hist, float* __restrict__ h_fin,
             float* __restrict__ c_fin, int steps) {
    extern __shared__ float sm[];
    float4* Us4  = (float4*)sm;            // 128c x 64 quads, swizzled
    float*  Usf  = sm;
    float*  hbuf = sm + 128 * 256;         // [2b][256]
    float*  zp   = hbuf + 512;             // [4hf][2b*128c]
    float*  zs   = zp + 1024;              // [2b][128c]
    float*  zxs  = zs + 256;               // [2b][128c]
    float*  hown = zxs + 256;              // [2buf][2b][32ul]

    const int tid = threadIdx.x;
    uint32_t rk; asm("mov.u32 %0, %%cluster_ctarank;" : "=r"(rk));
    const int r   = (int)rk;
    const int b0g = (blockIdx.x >> 3) * 2;

    for (int i = tid; i < 128 * 256; i += 512) {
        int c = i & 127, k = i >> 7;
        int g = c >> 5, ul = c & 31;
        float v = U[(size_t)k * 1024 + g * 256 + r * 32 + ul];
        int q = (k >> 2) ^ (c & 7);
        Usf[(c * 64 + q) * 4 + (k & 3)] = v;
    }
    float c_reg = 0.f;
    if (tid < 64) {
        int b = tid >> 5, ul = tid & 31;
        hown[(0 * 2 + b) * 32 + ul] = h0[(size_t)(b0g + b) * 256 + r * 32 + ul];
        c_reg = c0[(size_t)(b0g + b) * 256 + r * 32 + ul];
    }
    __syncthreads();
    CLUSTER_SYNC_();

    const uint32_t hown_u32 = smem_u32(hown);
    const int c  = tid & 127;
    const int hf = tid >> 7;
    const int cx = c & 7;
    int cur = 0;

    for (int s = 0; s < steps; s++) {
        // zx slice first (L2 latency overlaps the DSMEM pulls below)
        if (tid < 256) {
            int b = tid >> 7, cc = tid & 127;
            int g = cc >> 5, ul = cc & 31;
            zxs[tid] = zx[((size_t)(b0g + b) * steps + s) * 1024 + g * 256 + r * 32 + ul];
        }
        // pull h: 128 float4 remote loads (16B granules)
        if (tid < 128) {
            int b = tid >> 6, q = tid & 63;          // q -> units q*4..q*4+3
            uint32_t la = hown_u32 +
                (uint32_t)(((cur * 2 + b) * 32 + (q & 7) * 4) * 4);
            float4 hv = dsmem_ld_f32x4(la, (uint32_t)(q >> 3));
            *reinterpret_cast<float4*>(&hbuf[b * 256 + q * 4]) = hv;
        }
        __syncthreads();

        {   // gemv: thread (c,hf) covers k in [hf*64, hf*64+64), both batches
            float a00 = 0.f, a01 = 0.f, a02 = 0.f, a03 = 0.f;
            float a10 = 0.f, a11 = 0.f, a12 = 0.f, a13 = 0.f;
            const float4* h40 = (const float4*)&hbuf[0];
            const float4* h41 = (const float4*)&hbuf[256];
            const int kq0 = hf * 16;
#pragma unroll
            for (int t = 0; t < 16; t++) {
                int kq = kq0 + t;
                float4 u4 = Us4[c * 64 + (kq ^ cx)];
                float4 hA = h40[kq];
                float4 hB = h41[kq];
                a00 += u4.x * hA.x; a01 += u4.y * hA.y;
                a02 += u4.z * hA.z; a03 += u4.w * hA.w;
                a10 += u4.x * hB.x; a11 += u4.y * hB.y;
                a12 += u4.z * hB.z; a13 += u4.w * hB.w;
            }
            zp[hf * 256 + c]       = (a00 + a01) + (a02 + a03);
            zp[hf * 256 + 128 + c] = (a10 + a11) + (a12 + a13);
        }
        __syncthreads();
        if (tid < 256)
            zs[tid] = zxs[tid] + ((zp[tid] + zp[256 + tid]) + (zp[512 + tid] + zp[768 + tid]));
        __syncthreads();
        if (tid < 64) {
            int b = tid >> 5, ul = tid & 31;
            float iv = zs[b * 128 + 0 * 32 + ul];
            float fv = zs[b * 128 + 1 * 32 + ul];
            float gv = zs[b * 128 + 2 * 32 + ul];
            float ov = zs[b * 128 + 3 * 32 + ul];
            float ig = 1.f / (1.f + expf(-iv));
            float fg = 1.f / (1.f + expf(-fv));
            float og = 1.f / (1.f + expf(-ov));
            c_reg = fg * c_reg + ig * tanhf(gv);
            float h = og * tanhf(c_reg);
            hown[((cur ^ 1) * 2 + b) * 32 + ul] = h;
            hist[((size_t)(b0g + b) * steps + s) * 256 + r * 32 + ul] = h;
            if (s == steps - 1) {
                h_fin[(size_t)(b0g + b) * 256 + r * 32 + ul] = h;
                c_fin[(size_t)(b0g + b) * 256 + r * 32 + ul] = c_reg;
            }
        }
        CLUSTER_SYNC_();
        cur ^= 1;
    }
}

// ===== h0c0 = [eh;ec] @ We2d + be2d =====
__global__ void __launch_bounds__(256)
h0c0_kernel(const float* __restrict__ ehec, const float* __restrict__ We2d,
            const float* __restrict__ be2d, float* __restrict__ h0c0) {
    const int row = blockIdx.x, col = threadIdx.x;
    float a = be2d[col];
    const float* er = &ehec[row * 256];
#pragma unroll 16
    for (int k = 0; k < 256; k++) a += er[k] * We2d[k * 256 + col];
    h0c0[row * 256 + col] = a;
}

// ===== small SGEMM 128x64 tile, 8x4 micro =====
template <int MODE, int GATHER>
__global__ void __launch_bounds__(256)
sgemm_small(const float* __restrict__ A, const int* __restrict__ tokens,
            const float* __restrict__ emb, const float* __restrict__ B,
            float* __restrict__ C, int M, int N, int K,
            const float* __restrict__ bias) {
    __shared__ float As[16][132];
    __shared__ float Bs[16][68];
    const int tid  = threadIdx.x;
    const int row0 = blockIdx.y * 128;
    const int col0 = blockIdx.x * 64;
    const int tr   = tid >> 4, tc = tid & 15;

    float acc[8][4];
#pragma unroll
    for (int i = 0; i < 8; i++)
#pragma unroll
        for (int j = 0; j < 4; j++) acc[i][j] = 0.f;

    for (int k0 = 0; k0 < K; k0 += 16) {
#pragma unroll
        for (int h = 0; h < 2; h++) {
            int i4 = tid + 256 * h;
            int r  = i4 >> 2;
            int kq = (i4 & 3) * 4;
            const float* src;
            if (GATHER) src = &emb[(size_t)tokens[row0 + r] * K + k0 + kq];
            else        src = &A[(size_t)(row0 + r) * K + k0 + kq];
            float4 v = *reinterpret_cast<const float4*>(src);
            As[kq + 0][r] = v.x; As[kq + 1][r] = v.y;
            As[kq + 2][r] = v.z; As[kq + 3][r] = v.w;
        }
        {
            int kk = tid >> 4, n4 = (tid & 15) * 4;
            *reinterpret_cast<float4*>(&Bs[kk][n4]) =
                *reinterpret_cast<const float4*>(&B[(size_t)(k0 + kk) * N + col0 + n4]);
        }
        __syncthreads();
#pragma unroll
        for (int kk = 0; kk < 16; kk++) {
            float4 a0 = *reinterpret_cast<const float4*>(&As[kk][tr * 8]);
            float4 a1 = *reinterpret_cast<const float4*>(&As[kk][tr * 8 + 4]);
            float4 b0 = *reinterpret_cast<const float4*>(&Bs[kk][tc * 4]);
            float a[8] = {a0.x, a0.y, a0.z, a0.w, a1.x, a1.y, a1.z, a1.w};
            float b[4] = {b0.x, b0.y, b0.z, b0.w};
#pragma unroll
            for (int i = 0; i < 8; i++)
#pragma unroll
                for (int j = 0; j < 4; j++) acc[i][j] += a[i] * b[j];
        }
        __syncthreads();
    }
#pragma unroll
    for (int i = 0; i < 8; i++) {
        int r = row0 + tr * 8 + i;
#pragma unroll
        for (int j = 0; j < 4; j++) {
            int c = col0 + tc * 4 + j;
            float v = acc[i][j];
            if (bias) v += bias[c];
            if (MODE == 1) v = tanhf(v);
            C[(size_t)r * N + c] = v;
        }
    }
}

// ===== fused attention =====
__global__ void __launch_bounds__(256)
attn_mega(const float* __restrict__ dec, const float* __restrict__ enc,
          const float* __restrict__ Wattn, const float* __restrict__ Wout,
          const float* __restrict__ bout, const int* __restrict__ x_len,
          float* __restrict__ attn_out, float* __restrict__ rowsum) {
    __shared__ float dec_s[256];
    __shared__ float q_s[256];
    __shared__ float aw_s[256];
    __shared__ float red[8];
    const int bt = blockIdx.x, b = bt >> 4, tid = threadIdx.x;

    dec_s[tid] = dec[(size_t)bt * 256 + tid];
    if (tid == 0) rowsum[bt] = 1e-8f;
    __syncthreads();
    {
        float a = 0.f;
#pragma unroll 8
        for (int k = 0; k < 256; k++) a += dec_s[k] * Wattn[k * 256 + tid];
        q_s[tid] = a;
    }
    __syncthreads();
    const float* er = enc + ((size_t)b * SS + tid) * 256;
    float dot = 0.f;
#pragma unroll 4
    for (int k = 0; k < 256; k += 4) {
        float4 e = *reinterpret_cast<const float4*>(&er[k]);
        dot += q_s[k] * e.x + q_s[k + 1] * e.y + q_s[k + 2] * e.z + q_s[k + 3] * e.w;
    }
    const int len = x_len[b];
    float sc = (tid < len) ? dot : -1e30f;
    float m = sc;
#pragma unroll
    for (int o = 16; o; o >>= 1) m = fmaxf(m, __shfl_xor_sync(~0u, m, o));
    if ((tid & 31) == 0) red[tid >> 5] = m;
    __syncthreads();
    float mx = red[0];
#pragma unroll
    for (int w = 1; w < 8; w++) mx = fmaxf(mx, red[w]);
    __syncthreads();
    float e = (tid < len) ? __expf(sc - mx) : 0.f;
    float sm = e;
#pragma unroll
    for (int o = 16; o; o >>= 1) sm += __shfl_xor_sync(~0u, sm, o);
    if ((tid & 31) == 0) red[tid >> 5] = sm;
    __syncthreads();
    float tot = 0.f;
#pragma unroll
    for (int w = 0; w < 8; w++) tot += red[w];
    aw_s[tid] = e / tot;
    __syncthreads();
    float cx = 0.f;
    const float* eb = enc + (size_t)b * SS * 256 + tid;
#pragma unroll 8
    for (int s = 0; s < SS; s++) cx += aw_s[s] * eb[(size_t)s * 256];
    __syncthreads();
    q_s[tid] = cx;
    __syncthreads();
    float a2 = bout[tid];
#pragma unroll 8
    for (int k = 0; k < 256; k++) a2 += q_s[k] * Wout[k * 256 + tid];
#pragma unroll 8
    for (int k = 0; k < 256; k++) a2 += dec_s[k] * Wout[(256 + k) * 256 + tid];
    attn_out[(size_t)bt * 256 + tid] = tanhf(a2);
}

// ===== vocab GEMM (bf16 mma) =====
__device__ __forceinline__ void ldsm_x4(uint32_t* r, uint32_t addr) {
    asm volatile("ldmatrix.sync.aligned.m8n8.x4.shared.b16 {%0,%1,%2,%3}, [%4];"
                 : "=r"(r[0]), "=r"(r[1]), "=r"(r[2]), "=r"(r[3]) : "r"(addr));
}
__device__ __forceinline__ void ldsm_x2_trans(uint32_t* r, uint32_t addr) {
    asm volatile("ldmatrix.sync.aligned.m8n8.x2.trans.shared.b16 {%0,%1}, [%2];"
                 : "=r"(r[0]), "=r"(r[1]) : "r"(addr));
}
__device__ __forceinline__ void mma_bf16(float* d, const uint32_t* a, const uint32_t* b) {
    asm volatile("mma.sync.aligned.m16n8k16.row.col.f32.bf16.bf16.f32 "
                 "{%0,%1,%2,%3}, {%4,%5,%6,%7}, {%8,%9}, {%0,%1,%2,%3};"
                 : "+f"(d[0]), "+f"(d[1]), "+f"(d[2]), "+f"(d[3])
                 : "r"(a[0]), "r"(a[1]), "r"(a[2]), "r"(a[3]), "r"(b[0]), "r"(b[1]));
}

__global__ void __launch_bounds__(256)
vocab_kernel(const float* __restrict__ A, const float* __restrict__ Wgen,
             float* __restrict__ out, float* __restrict__ rowsum) {
    extern __shared__ char dsm[];
    __nv_bfloat16* Bsh = (__nv_bfloat16*)dsm;
    __nv_bfloat16* Ash = (__nv_bfloat16*)(dsm + 256 * BSTR * 2);
    float* rsumsh = (float*)(dsm + 256 * BSTR * 2 + 64 * ASTR * 2);

    const int tid  = threadIdx.x;
    const int lane = tid & 31, wid = tid >> 5;
    const int n0   = blockIdx.x * 128;
    const int m_off = (wid >> 2) * 32, n_off = (wid & 3) * 32;

    for (int i = tid; i < 256 * 32; i += 256) {
        int k = i >> 5, n4 = (i & 31) << 2, gn = n0 + n4;
        float4 v;
        if (gn + 3 < VV) {
            v = *reinterpret_cast<const float4*>(&Wgen[(size_t)k * VV + gn]);
        } else {
            v.x = (gn + 0 < VV) ? Wgen[(size_t)k * VV + gn + 0] : 0.f;
            v.y = (gn + 1 < VV) ? Wgen[(size_t)k * VV + gn + 1] : 0.f;
            v.z = (gn + 2 < VV) ? Wgen[(size_t)k * VV + gn + 2] : 0.f;
            v.w = (gn + 3 < VV) ? Wgen[(size_t)k * VV + gn + 3] : 0.f;
        }
        __nv_bfloat162* dst = reinterpret_cast<__nv_bfloat162*>(&Bsh[k * BSTR + n4]);
        dst[0] = __floats2bfloat162_rn(v.x, v.y);
        dst[1] = __floats2bfloat162_rn(v.z, v.w);
    }
    if (tid < 64) rsumsh[tid] = 0.f;
    __syncthreads();

    for (int mb = 0; mb < 8; mb++) {
        const int m0 = mb * 64;
        for (int i = tid; i < 64 * 64; i += 256) {
            int r = i >> 6, k4 = (i & 63) << 2;
            float4 v = *reinterpret_cast<const float4*>(&A[(size_t)(m0 + r) * 256 + k4]);
            __nv_bfloat162* dst = reinterpret_cast<__nv_bfloat162*>(&Ash[r * ASTR + k4]);
            dst[0] = __floats2bfloat162_rn(v.x, v.y);
            dst[1] = __floats2bfloat162_rn(v.z, v.w);
        }
        __syncthreads();

        float acc[2][4][4];
#pragma unroll
        for (int mf = 0; mf < 2; mf++)
#pragma unroll
            for (int nf = 0; nf < 4; nf++)
#pragma unroll
                for (int q = 0; q < 4; q++) acc[mf][nf][q] = 0.f;

#pragma unroll
        for (int ks = 0; ks < 16; ks++) {
            const int k0 = ks * 16;
            uint32_t afr[2][4], bfr[4][2];
#pragma unroll
            for (int mf = 0; mf < 2; mf++)
                ldsm_x4(afr[mf], smem_u32(
                    &Ash[(m_off + mf * 16 + (lane & 15)) * ASTR + k0 + (lane >> 4) * 8]));
#pragma unroll
            for (int nf = 0; nf < 4; nf++)
                ldsm_x2_trans(bfr[nf], smem_u32(
                    &Bsh[(k0 + (lane & 15)) * BSTR + n_off + nf * 8]));
#pragma unroll
            for (int mf = 0; mf < 2; mf++)
#pragma unroll
                for (int nf = 0; nf < 4; nf++)
                    mma_bf16(acc[mf][nf], afr[mf], bfr[nf]);
        }

        float psum[4] = {0.f, 0.f, 0.f, 0.f};
#pragma unroll
        for (int mf = 0; mf < 2; mf++) {
            int gr0 = m0 + m_off + mf * 16 + (lane >> 2);
#pragma unroll
            for (int nf = 0; nf < 4; nf++) {
                int gc = n0 + n_off + nf * 8 + (lane & 3) * 2;
                float v0 = acc[mf][nf][0], v1 = acc[mf][nf][1];
                float v2 = acc[mf][nf][2], v3 = acc[mf][nf][3];
                if (gc + 1 < VV) {
                    *reinterpret_cast<float2*>(&out[(size_t)gr0 * VO + gc]) = make_float2(v0, v1);
                    *reinterpret_cast<float2*>(&out[(size_t)(gr0 + 8) * VO + gc]) = make_float2(v2, v3);
                    psum[mf * 2 + 0] += __expf(v0) + __expf(v1);
                    psum[mf * 2 + 1] += __expf(v2) + __expf(v3);
                } else if (gc < VV) {
                    out[(size_t)gr0 * VO + gc] = v0;
                    out[(size_t)(gr0 + 8) * VO + gc] = v2;
                    psum[mf * 2 + 0] += __expf(v0);
                    psum[mf * 2 + 1] += __expf(v2);
                }
            }
        }
        {
            int lr = m_off + (lane >> 2);
            atomicAdd(&rsumsh[lr + 0],  psum[0]);
            atomicAdd(&rsumsh[lr + 8],  psum[1]);
            atomicAdd(&rsumsh[lr + 16], psum[2]);
            atomicAdd(&rsumsh[lr + 24], psum[3]);
        }
        __syncthreads();
        if (tid < 64) {
            atomicAdd(&rowsum[m0 + tid], rsumsh[tid]);
            rsumsh[tid] = 0.f;
        }
        __syncthreads();
    }
}

__global__ void copyzero_kernel(float* __restrict__ copyacc, const int* __restrict__ xov,
                                const int* __restrict__ x_len) {
    const int bt = blockIdx.x, b = bt >> 4, s = threadIdx.x;
    if (s < x_len[b]) copyacc[(size_t)bt * VO + xov[b * SS + s]] = 0.f;
}

__global__ void __launch_bounds__(256)
copy_scatter_kernel(const float* __restrict__ encWc, const float* __restrict__ attn,
                    const int* __restrict__ xov, const int* __restrict__ x_len,
                    float* __restrict__ copyacc, float* __restrict__ rowsum) {
    __shared__ float a[256];
    const int bt = blockIdx.x, b = bt >> 4, tid = threadIdx.x;
    a[tid] = attn[(size_t)bt * 256 + tid];
    __syncthreads();
    if (tid < x_len[b]) {
        const float* r = encWc + ((size_t)b * SS + tid) * 256;
        float dot = 0.f;
#pragma unroll 4
        for (int k = 0; k < 256; k += 4) {
            float4 e = *reinterpret_cast<const float4*>(&r[k]);
            dot += a[k] * e.x + a[k + 1] * e.y + a[k + 2] * e.z + a[k + 3] * e.w;
        }
        float v = expf(dot);
        atomicAdd(&copyacc[(size_t)bt * VO + xov[b * SS + tid]], v);
        atomicAdd(&rowsum[bt], v);
    }
}

__global__ void fixval_kernel(const float* __restrict__ out, const float* __restrict__ copyacc,
                              const int* __restrict__ xov, const int* __restrict__ x_len,
                              float* __restrict__ fixval) {
    const int bt = blockIdx.x, b = bt >> 4, s = threadIdx.x;
    if (s < x_len[b]) {
        int idx = xov[b * SS + s];
        float base = (idx < VV) ? expf(out[(size_t)bt * VO + idx]) : 1e-10f;
        fixval[bt * SS + s] = logf(base + copyacc[(size_t)bt * VO + idx]);
    }
}

__global__ void logz_kernel(const float* __restrict__ rs, float* __restrict__ lz) {
    int i = threadIdx.x + blockIdx.x * blockDim.x;
    if (i < BB * TT) lz[i] = logf(rs[i]);
}

__global__ void finalize_kernel(float* __restrict__ out, const float* __restrict__ lz) {
    const int row = blockIdx.y;
    const int c4  = (blockIdx.x * 256 + threadIdx.x) * 4;
    if (c4 >= VO) return;
    float z = lz[row];
    float* p = out + (size_t)row * VO + c4;
    if (c4 + 3 < VV) {
        float4 v = *reinterpret_cast<float4*>(p);
        v.x -= z; v.y -= z; v.z -= z; v.w -= z;
        *reinterpret_cast<float4*>(p) = v;
    } else {
#pragma unroll
        for (int j = 0; j < 4; j++) {
            int c = c4 + j;
            if (c < VO) p[j] = (c < VV) ? p[j] - z : LOG1EM10 - z;
        }
    }
}

__global__ void fixwrite_kernel(float* __restrict__ out, const float* __restrict__ fixval,
                                const float* __restrict__ lz, const int* __restrict__ xov,
                                const int* __restrict__ x_len) {
    const int bt = blockIdx.x, b = bt >> 4, s = threadIdx.x;
    if (s < x_len[b]) {
        int idx = xov[b * SS + s];
        out[(size_t)bt * VO + idx] = fixval[bt * SS + s] - lz[bt];
    }
}

extern "C" void kernel_launch(void* const* d_in, const int* in_sizes, int n_in,
                              void* d_out, int out_size) {
    const int*   x     = (const int*)d_in[0];
    const int*   xov   = (const int*)d_in[1];
    const int*   xlen  = (const int*)d_in[2];
    const int*   dx    = (const int*)d_in[3];
    const float* emb   = (const float*)d_in[4];
    const float* Wenc  = (const float*)d_in[5];
    const float* Uenc  = (const float*)d_in[6];
    const float* benc  = (const float*)d_in[7];
    const float* We2d  = (const float*)d_in[8];
    const float* be2d  = (const float*)d_in[9];
    const float* Wdec  = (const float*)d_in[10];
    const float* Udec  = (const float*)d_in[11];
    const float* bdec  = (const float*)d_in[12];
    const float* Wattn = (const float*)d_in[13];
    const float* Wout  = (const float*)d_in[14];
    const float* bout  = (const float*)d_in[15];
    const float* Wgen  = (const float*)d_in[16];
    const float* Wcopy = (const float*)d_in[17];
    const float* bcopy = (const float*)d_in[18];
    float* out = (float*)d_out;
    (void)in_sizes; (void)n_in; (void)out_size;

    void* p;
    cudaGetSymbolAddress(&p, d_zx_enc);  float* s_zx_enc  = (float*)p;
    cudaGetSymbolAddress(&p, d_zx_dec);  float* s_zx_dec  = (float*)p;
    cudaGetSymbolAddress(&p, d_enc_out); float* s_enc_out = (float*)p;
    cudaGetSymbolAddress(&p, d_dec_out); float* s_dec_out = (float*)p;
    cudaGetSymbolAddress(&p, d_ehec);    float* s_ehec    = (float*)p;
    cudaGetSymbolAddress(&p, d_h0c0);    float* s_h0c0    = (float*)p;
    cudaGetSymbolAddress(&p, d_encWc);   float* s_encWc   = (float*)p;
    cudaGetSymbolAddress(&p, d_attn);    float* s_attn    = (float*)p;
    cudaGetSymbolAddress(&p, d_rowsum);  float* s_rowsum  = (float*)p;
    cudaGetSymbolAddress(&p, d_logz);    float* s_logz    = (float*)p;
    cudaGetSymbolAddress(&p, d_fixval);  float* s_fixval  = (float*)p;
    cudaGetSymbolAddress(&p, d_copyacc); float* s_copyacc = (float*)p;
    cudaGetSymbolAddress(&p, d_zero);    float* s_zero    = (float*)p;

    cudaFuncSetAttribute(vocab_kernel,
                         cudaFuncAttributeMaxDynamicSharedMemorySize, VOCAB_SMEM + 256);
    cudaFuncSetAttribute(lstm_cluster,
                         cudaFuncAttributeMaxDynamicSharedMemorySize, LSTM_SMEM_BYTES);

    // 1-2. zx precompute (embedding gather fused)
    {
        dim3 g(1024 / 64, (BB * SS) / 128);
        sgemm_small<0, 1><<<g, 256>>>(nullptr, x, emb, Wenc, s_zx_enc,
                                      BB * SS, 4 * HH, EE, benc);
    }
    {
        dim3 g(1024 / 64, (BB * TT) / 128);
        sgemm_small<0, 1><<<g, 256>>>(nullptr, dx, emb, Wdec, s_zx_dec,
                                      BB * TT, 4 * HH, EE, bdec);
    }
    // 3. copyzero (dependency-free; placed here so encoder LSTM = launch #4 for ncu)
    copyzero_kernel<<<BB * TT, 256>>>(s_copyacc, xov, xlen);
    // 4. encoder LSTM (clustered)   [PROFILED]
    lstm_cluster<<<128, 512, LSTM_SMEM_BYTES>>>(
        s_zx_enc, Uenc, s_zero, s_zero, s_enc_out,
        s_ehec, s_ehec + BB * HH, SS);
    // 5. h0/c0
    h0c0_kernel<<<64, 256>>>(s_ehec, We2d, be2d, s_h0c0);
    // 6. decoder LSTM (final h,c -> output tail)
    lstm_cluster<<<128, 512, LSTM_SMEM_BYTES>>>(
        s_zx_dec, Udec, s_h0c0, s_h0c0 + BB * HH, s_dec_out,
        out + BTVO, out + BTVO + BB * HH, TT);
    // 7. fused attention (also inits rowsum)
    attn_mega<<<BB * TT, 256>>>(s_dec_out, s_enc_out, Wattn, Wout, bout, xlen,
                                s_attn, s_rowsum);
    // 8. vocab GEMM (tensor cores)
    vocab_kernel<<<(VV + 127) / 128, 256, VOCAB_SMEM>>>(s_attn, Wgen, out, s_rowsum);
    // 9. encWc = tanh(enc_out @ Wcopy + bcopy)
    {
        dim3 g(256 / 64, (BB * SS) / 128);
        sgemm_small<1, 0><<<g, 256>>>(s_enc_out, nullptr, nullptr, Wcopy, s_encWc,
                                      BB * SS, HH, HH, bcopy);
    }
    // 10. scatter copy scores
    copy_scatter_kernel<<<BB * TT, 256>>>(s_encWc, s_attn, xov, xlen, s_copyacc, s_rowsum);
    // 11. fixval (raw logits + copy mass)
    fixval_kernel<<<BB * TT, 256>>>(out, s_copyacc, xov, xlen, s_fixval);
    // 12. logZ
    logz_kernel<<<2, 256>>>(s_rowsum, s_logz);
    // 13. normalize
    {
        dim3 g((VO + 1023) / 1024, BB * TT);
        finalize_kernel<<<g, 256>>>(out, s_logz);
    }
    // 14. touched entries
    fixwrite_kernel<<<BB * TT, 256>>>(out, s_fixval, s_logz, xov, xlen);
}

// round 9
// speedup vs baseline: 1.6975x; 1.0743x over previous
#include <cuda_runtime.h>
#include <cuda_bf16.h>
#include <math.h>
#include <stdint.h>

#define VV    50000
#define OOV_N 100
#define VO    50100
#define EE    128
#define HH    256
#define BB    32
#define SS    256
#define TT    16
#define BTVO  ((size_t)BB * TT * VO)
#define LOG1EM10 (-23.025850929940457f)

#define BSTR 136
#define ASTR 264
#define VOCAB_SMEM (256*BSTR*2 + 64*ASTR*2 + 64*4)

// lstm smem floats: U^T 32768 + hbuf 1024 (2 buf x 512) + zp 1024 + zs 256 + zxs 512
#define LSTM_SMEM_FLOATS (32768 + 1024 + 1024 + 256 + 512)
#define LSTM_SMEM_BYTES  (LSTM_SMEM_FLOATS * 4)   // 142,336 B

__device__ float d_zx_enc[(size_t)BB * SS * 4 * HH];
__device__ float d_zx_dec[BB * TT * 4 * HH];
__device__ float d_enc_out[(size_t)BB * SS * HH];
__device__ float d_dec_out[BB * TT * HH];
__device__ float d_ehec[2 * BB * HH];
__device__ float d_h0c0[2 * BB * HH];
__device__ float d_encWc[(size_t)BB * SS * HH];
__device__ float d_attn[BB * TT * HH];
__device__ float d_rowsum[BB * TT];
__device__ float d_logz[BB * TT];
__device__ float d_fixval[BB * TT * SS];
__device__ float d_copyacc[BTVO];
__device__ float d_zero[BB * HH];

__device__ __forceinline__ uint32_t smem_u32(const void* p) {
    return (uint32_t)__cvta_generic_to_shared(p);
}
__device__ __forceinline__ void dsmem_st_f32(uint32_t laddr, uint32_t rank, float v) {
    uint32_t ra;
    asm volatile("mapa.shared::cluster.u32 %0, %1, %2;" : "=r"(ra) : "r"(laddr), "r"(rank));
    asm volatile("st.shared::cluster.f32 [%0], %1;" :: "r"(ra), "f"(v) : "memory");
}
#define CLUSTER_SYNC_() do { \
    asm volatile("barrier.cluster.arrive.aligned;" ::: "memory"); \
    asm volatile("barrier.cluster.wait.aligned;" ::: "memory"); \
} while (0)

__device__ __forceinline__ float sigmoid_fast(float x) {
    return 1.f / (1.f + __expf(-x));
}
__device__ __forceinline__ float tanh_fast(float x) {
    return 2.f / (1.f + __expf(-2.f * x)) - 1.f;
}

// ===== cluster LSTM: 16 clusters x 8 CTAs, 512 thr. Cluster owns 2 batches;
// CTA rank r owns gate-cols g*256 + r*32 + ul. U^T resident in smem
// (kq-major: warp loads 512B contiguous, conflict-free). h exchanged by
// PUSH (st.shared::cluster into peers' double-buffered hbuf) + barrier.cluster.
__global__ void __launch_bounds__(512, 1) __cluster_dims__(8, 1, 1)
lstm_cluster(const float* __restrict__ zx, const float* __restrict__ U,
             const float* __restrict__ h0, const float* __restrict__ c0,
             float* __restrict__ hist, float* __restrict__ h_fin,
             float* __restrict__ c_fin, int steps) {
    extern __shared__ float sm[];
    float4* Us4  = (float4*)sm;            // U^T: [kq 0..63][c 0..127] float4
    float*  hbuf = sm + 32768;             // [2 buf][2 b][256 u]
    float*  zp   = hbuf + 1024;            // [4 hf][2 b * 128 c]
    float*  zs   = zp + 1024;              // [2 b][128 c]
    float*  zxs  = zs + 256;               // [2 buf][256]

    const int tid = threadIdx.x;
    uint32_t rk; asm("mov.u32 %0, %%cluster_ctarank;" : "=r"(rk));
    const int r   = (int)rk;
    const int b0g = (blockIdx.x >> 3) * 2;

    // load U slice transposed: Us4T[k>>2][c], component k&3
    for (int i = tid; i < 128 * 256; i += 512) {
        int k = i >> 7, c = i & 127;
        float v = U[(size_t)k * 1024 + (c >> 5) * 256 + r * 32 + (c & 31)];
        sm[((k >> 2) * 128 + c) * 4 + (k & 3)] = v;
    }
    // init hbuf[0] with full h (2 batches x 256), each CTA locally
    {
        int b = tid >> 8, u = tid & 255;
        hbuf[b * 256 + u] = h0[(size_t)(b0g + b) * 256 + u];
    }
    float c_reg = 0.f;
    if (tid < 64) {
        int b = tid >> 5, ul = tid & 31;
        c_reg = c0[(size_t)(b0g + b) * 256 + r * 32 + ul];
    }
    // preload zxs[0]
    if (tid < 256) {
        int b = tid >> 7, cc = tid & 127;
        zxs[tid] = zx[((size_t)(b0g + b) * steps) * 1024 + (cc >> 5) * 256 + r * 32 + (cc & 31)];
    }
    __syncthreads();

    const int c  = tid & 127;
    const int hf = tid >> 7;
    const uint32_t hb_u32 = smem_u32(hbuf);

    for (int s = 0; s < steps; s++) {
        const int cur = s & 1, nxt = cur ^ 1;

        // prefetch zx for step s+1 (latency hidden under gemv)
        if (tid < 256 && s + 1 < steps) {
            int b = tid >> 7, cc = tid & 127;
            zxs[nxt * 256 + tid] =
                zx[((size_t)(b0g + b) * steps + (s + 1)) * 1024 + (cc >> 5) * 256 + r * 32 + (cc & 31)];
        }

        {   // gemv: thread (c,hf) covers kq in [hf*16, hf*16+16), both batches
            float a00 = 0.f, a01 = 0.f, a02 = 0.f, a03 = 0.f;
            float a10 = 0.f, a11 = 0.f, a12 = 0.f, a13 = 0.f;
            const float4* h40 = (const float4*)&hbuf[cur * 512];
            const float4* h41 = (const float4*)&hbuf[cur * 512 + 256];
            const int kq0 = hf * 16;
#pragma unroll
            for (int t = 0; t < 16; t++) {
                int kq = kq0 + t;
                float4 u4 = Us4[kq * 128 + c];   // contiguous per warp: conflict-free
                float4 hA = h40[kq];             // warp-uniform: broadcast
                float4 hB = h41[kq];
                a00 += u4.x * hA.x; a01 += u4.y * hA.y;
                a02 += u4.z * hA.z; a03 += u4.w * hA.w;
                a10 += u4.x * hB.x; a11 += u4.y * hB.y;
                a12 += u4.z * hB.z; a13 += u4.w * hB.w;
            }
            zp[hf * 256 + c]       = (a00 + a01) + (a02 + a03);
            zp[hf * 256 + 128 + c] = (a10 + a11) + (a12 + a13);
        }
        __syncthreads();
        if (tid < 256)
            zs[tid] = zxs[cur * 256 + tid] +
                      ((zp[tid] + zp[256 + tid]) + (zp[512 + tid] + zp[768 + tid]));
        __syncthreads();
        if (tid < 64) {
            int b = tid >> 5, ul = tid & 31;
            float iv = zs[b * 128 + 0 * 32 + ul];
            float fv = zs[b * 128 + 1 * 32 + ul];
            float gv = zs[b * 128 + 2 * 32 + ul];
            float ov = zs[b * 128 + 3 * 32 + ul];
            float ig = sigmoid_fast(iv);
            float fg = sigmoid_fast(fv);
            float og = sigmoid_fast(ov);
            c_reg = fg * c_reg + ig * tanh_fast(gv);
            float h = og * tanh_fast(c_reg);
            // push h to all 8 CTAs' hbuf[nxt] (incl. self)
            uint32_t off = hb_u32 + (uint32_t)((nxt * 512 + b * 256 + r * 32 + ul) * 4);
#pragma unroll
            for (int t = 0; t < 8; t++) dsmem_st_f32(off, (uint32_t)t, h);
            hist[((size_t)(b0g + b) * steps + s) * 256 + r * 32 + ul] = h;
            if (s == steps - 1) {
                h_fin[(size_t)(b0g + b) * 256 + r * 32 + ul] = h;
                c_fin[(size_t)(b0g + b) * 256 + r * 32 + ul] = c_reg;
            }
        }
        CLUSTER_SYNC_();   // release pushes + backpressure
    }
}

// ===== h0c0 = [eh;ec] @ We2d + be2d =====
__global__ void __launch_bounds__(256)
h0c0_kernel(const float* __restrict__ ehec, const float* __restrict__ We2d,
            const float* __restrict__ be2d, float* __restrict__ h0c0) {
    const int row = blockIdx.x, col = threadIdx.x;
    float a = be2d[col];
    const float* er = &ehec[row * 256];
#pragma unroll 16
    for (int k = 0; k < 256; k++) a += er[k] * We2d[k * 256 + col];
    h0c0[row * 256 + col] = a;
}

// ===== small SGEMM 128x64 tile, 8x4 micro =====
template <int MODE, int GATHER>
__global__ void __launch_bounds__(256)
sgemm_small(const float* __restrict__ A, const int* __restrict__ tokens,
            const float* __restrict__ emb, const float* __restrict__ B,
            float* __restrict__ C, int M, int N, int K,
            const float* __restrict__ bias) {
    __shared__ float As[16][132];
    __shared__ float Bs[16][68];
    const int tid  = threadIdx.x;
    const int row0 = blockIdx.y * 128;
    const int col0 = blockIdx.x * 64;
    const int tr   = tid >> 4, tc = tid & 15;

    float acc[8][4];
#pragma unroll
    for (int i = 0; i < 8; i++)
#pragma unroll
        for (int j = 0; j < 4; j++) acc[i][j] = 0.f;

    for (int k0 = 0; k0 < K; k0 += 16) {
#pragma unroll
        for (int h = 0; h < 2; h++) {
            int i4 = tid + 256 * h;
            int r  = i4 >> 2;
            int kq = (i4 & 3) * 4;
            const float* src;
            if (GATHER) src = &emb[(size_t)tokens[row0 + r] * K + k0 + kq];
            else        src = &A[(size_t)(row0 + r) * K + k0 + kq];
            float4 v = *reinterpret_cast<const float4*>(src);
            As[kq + 0][r] = v.x; As[kq + 1][r] = v.y;
            As[kq + 2][r] = v.z; As[kq + 3][r] = v.w;
        }
        {
            int kk = tid >> 4, n4 = (tid & 15) * 4;
            *reinterpret_cast<float4*>(&Bs[kk][n4]) =
                *reinterpret_cast<const float4*>(&B[(size_t)(k0 + kk) * N + col0 + n4]);
        }
        __syncthreads();
#pragma unroll
        for (int kk = 0; kk < 16; kk++) {
            float4 a0 = *reinterpret_cast<const float4*>(&As[kk][tr * 8]);
            float4 a1 = *reinterpret_cast<const float4*>(&As[kk][tr * 8 + 4]);
            float4 b0 = *reinterpret_cast<const float4*>(&Bs[kk][tc * 4]);
            float a[8] = {a0.x, a0.y, a0.z, a0.w, a1.x, a1.y, a1.z, a1.w};
            float b[4] = {b0.x, b0.y, b0.z, b0.w};
#pragma unroll
            for (int i = 0; i < 8; i++)
#pragma unroll
                for (int j = 0; j < 4; j++) acc[i][j] += a[i] * b[j];
        }
        __syncthreads();
    }
#pragma unroll
    for (int i = 0; i < 8; i++) {
        int r = row0 + tr * 8 + i;
#pragma unroll
        for (int j = 0; j < 4; j++) {
            int c = col0 + tc * 4 + j;
            float v = acc[i][j];
            if (bias) v += bias[c];
            if (MODE == 1) v = tanhf(v);
            C[(size_t)r * N + c] = v;
        }
    }
}

// ===== fused attention =====
__global__ void __launch_bounds__(256)
attn_mega(const float* __restrict__ dec, const float* __restrict__ enc,
          const float* __restrict__ Wattn, const float* __restrict__ Wout,
          const float* __restrict__ bout, const int* __restrict__ x_len,
          float* __restrict__ attn_out, float* __restrict__ rowsum) {
    __shared__ float dec_s[256];
    __shared__ float q_s[256];
    __shared__ float aw_s[256];
    __shared__ float red[8];
    const int bt = blockIdx.x, b = bt >> 4, tid = threadIdx.x;

    dec_s[tid] = dec[(size_t)bt * 256 + tid];
    if (tid == 0) rowsum[bt] = 1e-8f;
    __syncthreads();
    {
        float a = 0.f;
#pragma unroll 8
        for (int k = 0; k < 256; k++) a += dec_s[k] * Wattn[k * 256 + tid];
        q_s[tid] = a;
    }
    __syncthreads();
    const float* er = enc + ((size_t)b * SS + tid) * 256;
    float dot = 0.f;
#pragma unroll 4
    for (int k = 0; k < 256; k += 4) {
        float4 e = *reinterpret_cast<const float4*>(&er[k]);
        dot += q_s[k] * e.x + q_s[k + 1] * e.y + q_s[k + 2] * e.z + q_s[k + 3] * e.w;
    }
    const int len = x_len[b];
    float sc = (tid < len) ? dot : -1e30f;
    float m = sc;
#pragma unroll
    for (int o = 16; o; o >>= 1) m = fmaxf(m, __shfl_xor_sync(~0u, m, o));
    if ((tid & 31) == 0) red[tid >> 5] = m;
    __syncthreads();
    float mx = red[0];
#pragma unroll
    for (int w = 1; w < 8; w++) mx = fmaxf(mx, red[w]);
    __syncthreads();
    float e = (tid < len) ? __expf(sc - mx) : 0.f;
    float sm = e;
#pragma unroll
    for (int o = 16; o; o >>= 1) sm += __shfl_xor_sync(~0u, sm, o);
    if ((tid & 31) == 0) red[tid >> 5] = sm;
    __syncthreads();
    float tot = 0.f;
#pragma unroll
    for (int w = 0; w < 8; w++) tot += red[w];
    aw_s[tid] = e / tot;
    __syncthreads();
    float cx = 0.f;
    const float* eb = enc + (size_t)b * SS * 256 + tid;
#pragma unroll 8
    for (int s = 0; s < SS; s++) cx += aw_s[s] * eb[(size_t)s * 256];
    __syncthreads();
    q_s[tid] = cx;
    __syncthreads();
    float a2 = bout[tid];
#pragma unroll 8
    for (int k = 0; k < 256; k++) a2 += q_s[k] * Wout[k * 256 + tid];
#pragma unroll 8
    for (int k = 0; k < 256; k++) a2 += dec_s[k] * Wout[(256 + k) * 256 + tid];
    attn_out[(size_t)bt * 256 + tid] = tanhf(a2);
}

// ===== vocab GEMM (bf16 mma) =====
__device__ __forceinline__ void ldsm_x4(uint32_t* r, uint32_t addr) {
    asm volatile("ldmatrix.sync.aligned.m8n8.x4.shared.b16 {%0,%1,%2,%3}, [%4];"
                 : "=r"(r[0]), "=r"(r[1]), "=r"(r[2]), "=r"(r[3]) : "r"(addr));
}
__device__ __forceinline__ void ldsm_x2_trans(uint32_t* r, uint32_t addr) {
    asm volatile("ldmatrix.sync.aligned.m8n8.x2.trans.shared.b16 {%0,%1}, [%2];"
                 : "=r"(r[0]), "=r"(r[1]) : "r"(addr));
}
__device__ __forceinline__ void mma_bf16(float* d, const uint32_t* a, const uint32_t* b) {
    asm volatile("mma.sync.aligned.m16n8k16.row.col.f32.bf16.bf16.f32 "
                 "{%0,%1,%2,%3}, {%4,%5,%6,%7}, {%8,%9}, {%0,%1,%2,%3};"
                 : "+f"(d[0]), "+f"(d[1]), "+f"(d[2]), "+f"(d[3])
                 : "r"(a[0]), "r"(a[1]), "r"(a[2]), "r"(a[3]), "r"(b[0]), "r"(b[1]));
}

__global__ void __launch_bounds__(256)
vocab_kernel(const float* __restrict__ A, const float* __restrict__ Wgen,
             float* __restrict__ out, float* __restrict__ rowsum) {
    extern __shared__ char dsm[];
    __nv_bfloat16* Bsh = (__nv_bfloat16*)dsm;
    __nv_bfloat16* Ash = (__nv_bfloat16*)(dsm + 256 * BSTR * 2);
    float* rsumsh = (float*)(dsm + 256 * BSTR * 2 + 64 * ASTR * 2);

    const int tid  = threadIdx.x;
    const int lane = tid & 31, wid = tid >> 5;
    const int n0   = blockIdx.x * 128;
    const int m_off = (wid >> 2) * 32, n_off = (wid & 3) * 32;

    for (int i = tid; i < 256 * 32; i += 256) {
        int k = i >> 5, n4 = (i & 31) << 2, gn = n0 + n4;
        float4 v;
        if (gn + 3 < VV) {
            v = *reinterpret_cast<const float4*>(&Wgen[(size_t)k * VV + gn]);
        } else {
            v.x = (gn + 0 < VV) ? Wgen[(size_t)k * VV + gn + 0] : 0.f;
            v.y = (gn + 1 < VV) ? Wgen[(size_t)k * VV + gn + 1] : 0.f;
            v.z = (gn + 2 < VV) ? Wgen[(size_t)k * VV + gn + 2] : 0.f;
            v.w = (gn + 3 < VV) ? Wgen[(size_t)k * VV + gn + 3] : 0.f;
        }
        __nv_bfloat162* dst = reinterpret_cast<__nv_bfloat162*>(&Bsh[k * BSTR + n4]);
        dst[0] = __floats2bfloat162_rn(v.x, v.y);
        dst[1] = __floats2bfloat162_rn(v.z, v.w);
    }
    if (tid < 64) rsumsh[tid] = 0.f;
    __syncthreads();

    for (int mb = 0; mb < 8; mb++) {
        const int m0 = mb * 64;
        for (int i = tid; i < 64 * 64; i += 256) {
            int r = i >> 6, k4 = (i & 63) << 2;
            float4 v = *reinterpret_cast<const float4*>(&A[(size_t)(m0 + r) * 256 + k4]);
            __nv_bfloat162* dst = reinterpret_cast<__nv_bfloat162*>(&Ash[r * ASTR + k4]);
            dst[0] = __floats2bfloat162_rn(v.x, v.y);
            dst[1] = __floats2bfloat162_rn(v.z, v.w);
        }
        __syncthreads();

        float acc[2][4][4];
#pragma unroll
        for (int mf = 0; mf < 2; mf++)
#pragma unroll
            for (int nf = 0; nf < 4; nf++)
#pragma unroll
                for (int q = 0; q < 4; q++) acc[mf][nf][q] = 0.f;

#pragma unroll
        for (int ks = 0; ks < 16; ks++) {
            const int k0 = ks * 16;
            uint32_t afr[2][4], bfr[4][2];
#pragma unroll
            for (int mf = 0; mf < 2; mf++)
                ldsm_x4(afr[mf], smem_u32(
                    &Ash[(m_off + mf * 16 + (lane & 15)) * ASTR + k0 + (lane >> 4) * 8]));
#pragma unroll
            for (int nf = 0; nf < 4; nf++)
                ldsm_x2_trans(bfr[nf], smem_u32(
                    &Bsh[(k0 + (lane & 15)) * BSTR + n_off + nf * 8]));
#pragma unroll
            for (int mf = 0; mf < 2; mf++)
#pragma unroll
                for (int nf = 0; nf < 4; nf++)
                    mma_bf16(acc[mf][nf], afr[mf], bfr[nf]);
        }

        float psum[4] = {0.f, 0.f, 0.f, 0.f};
#pragma unroll
        for (int mf = 0; mf < 2; mf++) {
            int gr0 = m0 + m_off + mf * 16 + (lane >> 2);
#pragma unroll
            for (int nf = 0; nf < 4; nf++) {
                int gc = n0 + n_off + nf * 8 + (lane & 3) * 2;
                float v0 = acc[mf][nf][0], v1 = acc[mf][nf][1];
                float v2 = acc[mf][nf][2], v3 = acc[mf][nf][3];
                if (gc + 1 < VV) {
                    *reinterpret_cast<float2*>(&out[(size_t)gr0 * VO + gc]) = make_float2(v0, v1);
                    *reinterpret_cast<float2*>(&out[(size_t)(gr0 + 8) * VO + gc]) = make_float2(v2, v3);
                    psum[mf * 2 + 0] += __expf(v0) + __expf(v1);
                    psum[mf * 2 + 1] += __expf(v2) + __expf(v3);
                } else if (gc < VV) {
                    out[(size_t)gr0 * VO + gc] = v0;
                    out[(size_t)(gr0 + 8) * VO + gc] = v2;
                    psum[mf * 2 + 0] += __expf(v0);
                    psum[mf * 2 + 1] += __expf(v2);
                }
            }
        }
        {
            int lr = m_off + (lane >> 2);
            atomicAdd(&rsumsh[lr + 0],  psum[0]);
            atomicAdd(&rsumsh[lr + 8],  psum[1]);
            atomicAdd(&rsumsh[lr + 16], psum[2]);
            atomicAdd(&rsumsh[lr + 24], psum[3]);
        }
        __syncthreads();
        if (tid < 64) {
            atomicAdd(&rowsum[m0 + tid], rsumsh[tid]);
            rsumsh[tid] = 0.f;
        }
        __syncthreads();
    }
}

__global__ void copyzero_kernel(float* __restrict__ copyacc, const int* __restrict__ xov,
                                const int* __restrict__ x_len) {
    const int bt = blockIdx.x, b = bt >> 4, s = threadIdx.x;
    if (s < x_len[b]) copyacc[(size_t)bt * VO + xov[b * SS + s]] = 0.f;
}

__global__ void __launch_bounds__(256)
copy_scatter_kernel(const float* __restrict__ encWc, const float* __restrict__ attn,
                    const int* __restrict__ xov, const int* __restrict__ x_len,
                    float* __restrict__ copyacc, float* __restrict__ rowsum) {
    __shared__ float a[256];
    const int bt = blockIdx.x, b = bt >> 4, tid = threadIdx.x;
    a[tid] = attn[(size_t)bt * 256 + tid];
    __syncthreads();
    if (tid < x_len[b]) {
        const float* r = encWc + ((size_t)b * SS + tid) * 256;
        float dot = 0.f;
#pragma unroll 4
        for (int k = 0; k < 256; k += 4) {
            float4 e = *reinterpret_cast<const float4*>(&r[k]);
            dot += a[k] * e.x + a[k + 1] * e.y + a[k + 2] * e.z + a[k + 3] * e.w;
        }
        float v = expf(dot);
        atomicAdd(&copyacc[(size_t)bt * VO + xov[b * SS + tid]], v);
        atomicAdd(&rowsum[bt], v);
    }
}

__global__ void fixval_kernel(const float* __restrict__ out, const float* __restrict__ copyacc,
                              const int* __restrict__ xov, const int* __restrict__ x_len,
                              float* __restrict__ fixval) {
    const int bt = blockIdx.x, b = bt >> 4, s = threadIdx.x;
    if (s < x_len[b]) {
        int idx = xov[b * SS + s];
        float base = (idx < VV) ? expf(out[(size_t)bt * VO + idx]) : 1e-10f;
        fixval[bt * SS + s] = logf(base + copyacc[(size_t)bt * VO + idx]);
    }
}

__global__ void logz_kernel(const float* __restrict__ rs, float* __restrict__ lz) {
    int i = threadIdx.x + blockIdx.x * blockDim.x;
    if (i < BB * TT) lz[i] = logf(rs[i]);
}

__global__ void finalize_kernel(float* __restrict__ out, const float* __restrict__ lz) {
    const int row = blockIdx.y;
    const int c4  = (blockIdx.x * 256 + threadIdx.x) * 4;
    if (c4 >= VO) return;
    float z = lz[row];
    float* p = out + (size_t)row * VO + c4;
    if (c4 + 3 < VV) {
        float4 v = *reinterpret_cast<float4*>(p);
        v.x -= z; v.y -= z; v.z -= z; v.w -= z;
        *reinterpret_cast<float4*>(p) = v;
    } else {
#pragma unroll
        for (int j = 0; j < 4; j++) {
            int c = c4 + j;
            if (c < VO) p[j] = (c < VV) ? p[j] - z : LOG1EM10 - z;
        }
    }
}

__global__ void fixwrite_kernel(float* __restrict__ out, const float* __restrict__ fixval,
                                const float* __restrict__ lz, const int* __restrict__ xov,
                                const int* __restrict__ x_len) {
    const int bt = blockIdx.x, b = bt >> 4, s = threadIdx.x;
    if (s < x_len[b]) {
        int idx = xov[b * SS + s];
        out[(size_t)bt * VO + idx] = fixval[bt * SS + s] - lz[bt];
    }
}

extern "C" void kernel_launch(void* const* d_in, const int* in_sizes, int n_in,
                              void* d_out, int out_size) {
    const int*   x     = (const int*)d_in[0];
    const int*   xov   = (const int*)d_in[1];
    const int*   xlen  = (const int*)d_in[2];
    const int*   dx    = (const int*)d_in[3];
    const float* emb   = (const float*)d_in[4];
    const float* Wenc  = (const float*)d_in[5];
    const float* Uenc  = (const float*)d_in[6];
    const float* benc  = (const float*)d_in[7];
    const float* We2d  = (const float*)d_in[8];
    const float* be2d  = (const float*)d_in[9];
    const float* Wdec  = (const float*)d_in[10];
    const float* Udec  = (const float*)d_in[11];
    const float* bdec  = (const float*)d_in[12];
    const float* Wattn = (const float*)d_in[13];
    const float* Wout  = (const float*)d_in[14];
    const float* bout  = (const float*)d_in[15];
    const float* Wgen  = (const float*)d_in[16];
    const float* Wcopy = (const float*)d_in[17];
    const float* bcopy = (const float*)d_in[18];
    float* out = (float*)d_out;
    (void)in_sizes; (void)n_in; (void)out_size;

    void* p;
    cudaGetSymbolAddress(&p, d_zx_enc);  float* s_zx_enc  = (float*)p;
    cudaGetSymbolAddress(&p, d_zx_dec);  float* s_zx_dec  = (float*)p;
    cudaGetSymbolAddress(&p, d_enc_out); float* s_enc_out = (float*)p;
    cudaGetSymbolAddress(&p, d_dec_out); float* s_dec_out = (float*)p;
    cudaGetSymbolAddress(&p, d_ehec);    float* s_ehec    = (float*)p;
    cudaGetSymbolAddress(&p, d_h0c0);    float* s_h0c0    = (float*)p;
    cudaGetSymbolAddress(&p, d_encWc);   float* s_encWc   = (float*)p;
    cudaGetSymbolAddress(&p, d_attn);    float* s_attn    = (float*)p;
    cudaGetSymbolAddress(&p, d_rowsum);  float* s_rowsum  = (float*)p;
    cudaGetSymbolAddress(&p, d_logz);    float* s_logz    = (float*)p;
    cudaGetSymbolAddress(&p, d_fixval);  float* s_fixval  = (float*)p;
    cudaGetSymbolAddress(&p, d_copyacc); float* s_copyacc = (float*)p;
    cudaGetSymbolAddress(&p, d_zero);    float* s_zero    = (float*)p;

    cudaFuncSetAttribute(vocab_kernel,
                         cudaFuncAttributeMaxDynamicSharedMemorySize, VOCAB_SMEM + 256);
    cudaFuncSetAttribute(lstm_cluster,
                         cudaFuncAttributeMaxDynamicSharedMemorySize, LSTM_SMEM_BYTES);

    // 1-2. zx precompute (embedding gather fused)
    {
        dim3 g(1024 / 64, (BB * SS) / 128);
        sgemm_small<0, 1><<<g, 256>>>(nullptr, x, emb, Wenc, s_zx_enc,
                                      BB * SS, 4 * HH, EE, benc);
    }
    {
        dim3 g(1024 / 64, (BB * TT) / 128);
        sgemm_small<0, 1><<<g, 256>>>(nullptr, dx, emb, Wdec, s_zx_dec,
                                      BB * TT, 4 * HH, EE, bdec);
    }
    // 3. copyzero (dependency-free; keeps encoder LSTM = launch #4 for ncu)
    copyzero_kernel<<<BB * TT, 256>>>(s_copyacc, xov, xlen);
    // 4. encoder LSTM (clustered, push-based)   [PROFILED]
    lstm_cluster<<<128, 512, LSTM_SMEM_BYTES>>>(
        s_zx_enc, Uenc, s_zero, s_zero, s_enc_out,
        s_ehec, s_ehec + BB * HH, SS);
    // 5. h0/c0
    h0c0_kernel<<<64, 256>>>(s_ehec, We2d, be2d, s_h0c0);
    // 6. decoder LSTM (final h,c -> output tail)
    lstm_cluster<<<128, 512, LSTM_SMEM_BYTES>>>(
        s_zx_dec, Udec, s_h0c0, s_h0c0 + BB * HH, s_dec_out,
        out + BTVO, out + BTVO + BB * HH, TT);
    // 7. fused attention (also inits rowsum)
    attn_mega<<<BB * TT, 256>>>(s_dec_out, s_enc_out, Wattn, Wout, bout, xlen,
                                s_attn, s_rowsum);
    // 8. vocab GEMM (tensor cores)
    vocab_kernel<<<(VV + 127) / 128, 256, VOCAB_SMEM>>>(s_attn, Wgen, out, s_rowsum);
    // 9. encWc = tanh(enc_out @ Wcopy + bcopy)
    {
        dim3 g(256 / 64, (BB * SS) / 128);
        sgemm_small<1, 0><<<g, 256>>>(s_enc_out, nullptr, nullptr, Wcopy, s_encWc,
                                      BB * SS, HH, HH, bcopy);
    }
    // 10. scatter copy scores
    copy_scatter_kernel<<<BB * TT, 256>>>(s_encWc, s_attn, xov, xlen, s_copyacc, s_rowsum);
    // 11. fixval (raw logits + copy mass)
    fixval_kernel<<<BB * TT, 256>>>(out, s_copyacc, xov, xlen, s_fixval);
    // 12. logZ
    logz_kernel<<<2, 256>>>(s_rowsum, s_logz);
    // 13. normalize
    {
        dim3 g((VO + 1023) / 1024, BB * TT);
        finalize_kernel<<<g, 256>>>(out, s_logz);
    }
    // 14. touched entries
    fixwrite_kernel<<<BB * TT, 256>>>(out, s_fixval, s_logz, xov, xlen);
}